// round 9
// baseline (speedup 1.0000x reference)
#include <cuda_runtime.h>

#define M_TOK 4096
#define DM    64
#define NH    8
#define HD    8
#define DFF   256
#define NLAYER 4
#define KSPLIT 4

typedef unsigned long long u64;

// ---------------- scratch (device globals; no allocation allowed) ----------------
__device__ __align__(16) float g_X   [M_TOK*DM];
__device__ __align__(16) float g_QKV [3*NH*M_TOK*HD];
__device__ __align__(16) float g_F1  [M_TOK*DFF];
__device__ __align__(16) float g_PACC[KSPLIT*M_TOK*DM];
__device__ __align__(16) float g_PSUM[KSPLIT*NH*M_TOK];
__device__ float g_NX[M_TOK];
__device__ float g_NY[M_TOK];
__device__ float g_PART[3*128];
__device__ int   g_kd;

// ---------------- packed f32x2 helpers (SASS FFMA2: only reachable via PTX) ------
#define F2_FMA3(d,a,b,c) asm("fma.rn.f32x2 %0,%1,%2,%3;" : "=l"(d) : "l"(a),"l"(b),"l"(c))
#define F2_FMA(d,a,b)    asm("fma.rn.f32x2 %0,%1,%2,%0;" : "+l"(d) : "l"(a),"l"(b))
// Horner step: p = p*f + c   (dst is the multiplicand — distinct from F2_FMA!)
#define F2_HORN(p,f,c)   asm("fma.rn.f32x2 %0,%0,%1,%2;" : "+l"(p) : "l"(f),"l"(c))
#define F2_MUL(d,a,b)    asm("mul.rn.f32x2 %0,%1,%2;"    : "=l"(d) : "l"(a),"l"(b))
#define F2_ADD(d,a,b)    asm("add.rn.f32x2 %0,%1,%2;"    : "+l"(d) : "l"(a),"l"(b))
#define PACK2(d,lo,hi)   asm("mov.b64 %0,{%1,%2};" : "=l"(d) : "r"(lo),"r"(hi))
#define UNPACK2(lo,hi,s) asm("mov.b64 {%0,%1},%2;" : "=r"(lo),"=r"(hi) : "l"(s))

__device__ __forceinline__ u64 pairbits(unsigned x){
    u64 r; asm("mov.b64 %0,{%1,%1};" : "=l"(r) : "r"(x)); return r;
}

struct ExpC { u64 L2E, MAG, N1, c5, c4, c3, c2, c1, c0; };
__device__ __forceinline__ ExpC make_expc(){
    ExpC e;
    e.L2E = pairbits(0x3FB8AA3Bu);          // log2(e)
    e.MAG = pairbits(0x4B400000u);          // 12582912.f
    e.N1  = pairbits(0xBF800000u);          // -1.f
    e.c5  = pairbits(__float_as_uint(1.3333558146e-3f));
    e.c4  = pairbits(__float_as_uint(9.618129107e-3f));
    e.c3  = pairbits(__float_as_uint(5.550410866e-2f));
    e.c2  = pairbits(__float_as_uint(2.402264923e-1f));
    e.c1  = pairbits(__float_as_uint(6.9314718056e-1f));
    e.c0  = pairbits(0x3F800000u);          // 1.f
    return e;
}

// exp() on two packed floats, entirely on the FMA pipe. Inputs must be > -120.
__device__ __forceinline__ u64 pexp2(u64 s, const ExpC& C, unsigned& r0, unsigned& r1){
    u64 t, nfn, f, p;
    F2_FMA3(t,   s, C.L2E, C.MAG);   // round(x*log2e) in mantissa
    F2_FMA3(nfn, t, C.N1,  C.MAG);   // magic - t = -fn
    F2_FMA3(f,   s, C.L2E, nfn);     // frac in [-0.5, 0.5]
    F2_FMA3(p, C.c5, f, C.c4);       // p = c5*f + c4
    F2_HORN(p, f, C.c3);             // p = p*f + c3
    F2_HORN(p, f, C.c2);
    F2_HORN(p, f, C.c1);
    F2_HORN(p, f, C.c0);
    unsigned t0,t1,p0,p1;
    UNPACK2(t0,t1,t); UNPACK2(p0,p1,p);
    r0 = p0 + (t0 << 23);            // exponent splice: low 9 bits of magic are 0
    r1 = p1 + (t1 << 23);
    u64 r; PACK2(r, r0, r1);
    return r;
}

// ---------------- generic skinny GEMM: C = A[4096,K] @ W[ncols,K]^T + b ----------
// 8-row tiles (grid.x = 512), one warp per output row, f32x2 k-pair accumulation.
// ASRC 0: A from global; ASRC 1: A = split-K attention combine (PACC/PSUM).
// EPI 0: scatter to Q/K/V head layout (q scaled by 1/sqrt(hd))
// EPI 1: ReLU -> OUT[m*ldo + col]
// EPI 2: + residual, LayerNorm -> OUT[m*64 + col]
// EPI 4: + residual, LayerNorm, *mask -> OUT(dout), plus row norms NX/NY + kd detect
template<int KDIM, int EPI, int ASRC>
__global__ __launch_bounds__(256) void k_gemm(
    const float* __restrict__ A,
    const float* __restrict__ W,
    const float* __restrict__ bias,
    const float* __restrict__ RES,
    const float* __restrict__ lnw, const float* __restrict__ lnb,
    float* __restrict__ OUT, int ldo,
    const float* __restrict__ mask, const float* __restrict__ RGB)
{
    __shared__ __align__(16) float Asm[8][68];
    __shared__ __align__(16) float Wsm[64][68];
    const int tid = threadIdx.x;
    const int rb  = blockIdx.x * 8;
    const int cb  = blockIdx.y * 64;
    const int c0  = tid & 31;
    const int row = tid >> 5;              // one warp per output row
    u64 acc2[2] = {0, 0};

    #pragma unroll
    for (int ch = 0; ch < KDIM/64; ch++){
        if (tid < 128){
            int r = tid >> 4, kq = tid & 15;
            float4 v;
            if (ASRC == 0){
                v = ((const float4*)(A + (size_t)(rb + r)*KDIM + ch*64))[kq];
            } else {
                int m = rb + r;
                float4 a0 = *(const float4*)&g_PACC[(size_t)(0*M_TOK + m)*DM + kq*4];
                float4 a1 = *(const float4*)&g_PACC[(size_t)(1*M_TOK + m)*DM + kq*4];
                float4 a2 = *(const float4*)&g_PACC[(size_t)(2*M_TOK + m)*DM + kq*4];
                float4 a3 = *(const float4*)&g_PACC[(size_t)(3*M_TOK + m)*DM + kq*4];
                int h = kq >> 1;
                float s = g_PSUM[0*NH*M_TOK + h*M_TOK + m]
                        + g_PSUM[1*NH*M_TOK + h*M_TOK + m]
                        + g_PSUM[2*NH*M_TOK + h*M_TOK + m]
                        + g_PSUM[3*NH*M_TOK + h*M_TOK + m];
                float inv = 1.f / s;
                v.x = (a0.x+a1.x+a2.x+a3.x)*inv;
                v.y = (a0.y+a1.y+a2.y+a3.y)*inv;
                v.z = (a0.z+a1.z+a2.z+a3.z)*inv;
                v.w = (a0.w+a1.w+a2.w+a3.w)*inv;
            }
            *(float4*)&Asm[r][kq*4] = v;
        }
        #pragma unroll
        for (int idx = tid; idx < 4096; idx += 256){
            int c = idx >> 6, k = idx & 63;
            Wsm[c][k] = W[(size_t)(cb + c)*KDIM + ch*64 + k];
        }
        __syncthreads();
        #pragma unroll
        for (int k = 0; k < 64; k += 4){
            ulonglong2 a  = *(const ulonglong2*)&Asm[row][k];       // broadcast
            ulonglong2 w0 = *(const ulonglong2*)&Wsm[c0   ][k];
            ulonglong2 w1 = *(const ulonglong2*)&Wsm[c0+32][k];
            F2_FMA(acc2[0], a.x, w0.x); F2_FMA(acc2[0], a.y, w0.y);
            F2_FMA(acc2[1], a.x, w1.x); F2_FMA(acc2[1], a.y, w1.y);
        }
        __syncthreads();
    }

    const int m = rb + row;
    unsigned lo, hi;
    UNPACK2(lo, hi, acc2[0]);
    float v0 = __uint_as_float(lo) + __uint_as_float(hi) + bias[cb + c0];
    UNPACK2(lo, hi, acc2[1]);
    float v1 = __uint_as_float(lo) + __uint_as_float(hi) + bias[cb + c0 + 32];

    if (EPI == 0){
        const float qs = (blockIdx.y == 0) ? 0.35355339059327373f : 1.0f;
        int c = c0;
        OUT[(((int)blockIdx.y*NH + (c >> 3))*M_TOK + m)*HD + (c & 7)] = v0 * qs;
        c = c0 + 32;
        OUT[(((int)blockIdx.y*NH + (c >> 3))*M_TOK + m)*HD + (c & 7)] = v1 * qs;
    } else if (EPI == 1){
        OUT[(size_t)m*ldo + cb + c0]      = fmaxf(v0, 0.f);
        OUT[(size_t)m*ldo + cb + c0 + 32] = fmaxf(v1, 0.f);
    } else {
        v0 += RES[m*DM + c0];
        v1 += RES[m*DM + c0 + 32];
        float s = v0 + v1, s2 = fmaf(v0, v0, v1*v1);
        #pragma unroll
        for (int off = 16; off > 0; off >>= 1){
            s  += __shfl_xor_sync(0xffffffffu, s,  off);
            s2 += __shfl_xor_sync(0xffffffffu, s2, off);
        }
        float mean = s * (1.f/64.f);
        float var  = fmaf(-mean, mean, s2 * (1.f/64.f));
        float rstd = rsqrtf(var + 1e-5f);
        float o0 = (v0 - mean) * rstd * lnw[c0]      + lnb[c0];
        float o1 = (v1 - mean) * rstd * lnw[c0 + 32] + lnb[c0 + 32];
        if (EPI == 2){
            OUT[m*DM + c0]      = o0;
            OUT[m*DM + c0 + 32] = o1;
        } else {   // EPI 4: final layer — prune, emit output, row norms, kd detect
            float xv0 = o0 * mask[c0];
            float xv1 = o1 * mask[c0 + 32];
            OUT[m*DM + c0]      = xv0;
            OUT[m*DM + c0 + 32] = xv1;
            float yv0 = RGB[m*DM + c0], yv1 = RGB[m*DM + c0 + 32];
            float nx = fmaf(xv0, xv0, xv1*xv1);
            float ny = fmaf(yv0, yv0, yv1*yv1);
            #pragma unroll
            for (int off = 16; off > 0; off >>= 1){
                nx += __shfl_xor_sync(0xffffffffu, nx, off);
                ny += __shfl_xor_sync(0xffffffffu, ny, off);
            }
            if (c0 == 0){ g_NX[m] = nx; g_NY[m] = ny; }
            if (blockIdx.x == 0 && tid < 32){
                unsigned any = __ballot_sync(0xffffffffu, mask[32 + tid] != 0.f);
                if (tid == 0) g_kd = any ? 64 : 32;
            }
        }
    }
}

// ---------------- attention: no-max softmax, 4-way split-K, 2 queries/thread -----
// K tile stored pair-interleaved: Kp[jp*16 + d*2 + parity] so LDS.128 yields
// packed (k_even[d], k_odd[d]) operands directly.
__global__ __launch_bounds__(128) void k_attn(const float* __restrict__ QKV)
{
    __shared__ __align__(16) float  Kp[512*8];
    __shared__ __align__(16) float4 Vs[1024];
    const int tid = threadIdx.x;
    const int h   = blockIdx.y;
    const int ks  = blockIdx.z;
    const int m0  = blockIdx.x*256 + tid;
    const int m1  = m0 + 128;
    const float4* Qb = (const float4*)QKV;
    const float4* K4 = (const float4*)QKV + (size_t)(NH*M_TOK + h*M_TOK)*2;
    const float4* V4 = (const float4*)QKV + (size_t)(2*NH*M_TOK + h*M_TOK)*2;

    const ExpC C = make_expc();
    float4 qa0 = Qb[(size_t)(h*M_TOK + m0)*2], qa1 = Qb[(size_t)(h*M_TOK + m0)*2 + 1];
    float4 qb0 = Qb[(size_t)(h*M_TOK + m1)*2], qb1 = Qb[(size_t)(h*M_TOK + m1)*2 + 1];
    u64 qA[8], qB[8];
    qA[0]=pairbits(__float_as_uint(qa0.x)); qA[1]=pairbits(__float_as_uint(qa0.y));
    qA[2]=pairbits(__float_as_uint(qa0.z)); qA[3]=pairbits(__float_as_uint(qa0.w));
    qA[4]=pairbits(__float_as_uint(qa1.x)); qA[5]=pairbits(__float_as_uint(qa1.y));
    qA[6]=pairbits(__float_as_uint(qa1.z)); qA[7]=pairbits(__float_as_uint(qa1.w));
    qB[0]=pairbits(__float_as_uint(qb0.x)); qB[1]=pairbits(__float_as_uint(qb0.y));
    qB[2]=pairbits(__float_as_uint(qb0.z)); qB[3]=pairbits(__float_as_uint(qb0.w));
    qB[4]=pairbits(__float_as_uint(qb1.x)); qB[5]=pairbits(__float_as_uint(qb1.y));
    qB[6]=pairbits(__float_as_uint(qb1.z)); qB[7]=pairbits(__float_as_uint(qb1.w));

    u64 accA[4] = {0,0,0,0}, accB[4] = {0,0,0,0};
    u64 ssA = 0, ssB = 0;

    for (int kt = 0; kt < 2; kt++){
        int key0 = ks*1024 + kt*512;
        for (int idx = tid; idx < 1024; idx += 128){
            int j = idx >> 1, hf = idx & 1;
            float4 kv = K4[key0*2 + idx];
            float* dst = Kp + (j>>1)*16 + hf*8 + (j&1);
            dst[0]=kv.x; dst[2]=kv.y; dst[4]=kv.z; dst[6]=kv.w;
            Vs[idx] = V4[key0*2 + idx];
        }
        __syncthreads();
        const ulonglong2* vr = (const ulonglong2*)Vs;
        #pragma unroll 2
        for (int jp = 0; jp < 256; jp++){
            const ulonglong2* kr = (const ulonglong2*)(Kp + jp*16);
            ulonglong2 k01 = kr[0], k23 = kr[1], k45 = kr[2], k67 = kr[3];
            u64 sA, sB;
            F2_MUL(sA, qA[0], k01.x);
            F2_FMA(sA, qA[1], k01.y); F2_FMA(sA, qA[2], k23.x); F2_FMA(sA, qA[3], k23.y);
            F2_FMA(sA, qA[4], k45.x); F2_FMA(sA, qA[5], k45.y);
            F2_FMA(sA, qA[6], k67.x); F2_FMA(sA, qA[7], k67.y);
            F2_MUL(sB, qB[0], k01.x);
            F2_FMA(sB, qB[1], k01.y); F2_FMA(sB, qB[2], k23.x); F2_FMA(sB, qB[3], k23.y);
            F2_FMA(sB, qB[4], k45.x); F2_FMA(sB, qB[5], k45.y);
            F2_FMA(sB, qB[6], k67.x); F2_FMA(sB, qB[7], k67.y);
            unsigned a0r, a1r, b0r, b1r;
            u64 pA = pexp2(sA, C, a0r, a1r);
            u64 pB = pexp2(sB, C, b0r, b1r);
            F2_ADD(ssA, ssA, pA);
            F2_ADD(ssB, ssB, pB);
            u64 pA0 = pairbits(a0r), pA1 = pairbits(a1r);
            u64 pB0 = pairbits(b0r), pB1 = pairbits(b1r);
            ulonglong2 e0 = vr[4*jp],   e1 = vr[4*jp+1];   // even key d0-3, d4-7
            ulonglong2 o0 = vr[4*jp+2], o1 = vr[4*jp+3];   // odd key
            F2_FMA(accA[0], pA0, e0.x); F2_FMA(accA[1], pA0, e0.y);
            F2_FMA(accA[2], pA0, e1.x); F2_FMA(accA[3], pA0, e1.y);
            F2_FMA(accA[0], pA1, o0.x); F2_FMA(accA[1], pA1, o0.y);
            F2_FMA(accA[2], pA1, o1.x); F2_FMA(accA[3], pA1, o1.y);
            F2_FMA(accB[0], pB0, e0.x); F2_FMA(accB[1], pB0, e0.y);
            F2_FMA(accB[2], pB0, e1.x); F2_FMA(accB[3], pB0, e1.y);
            F2_FMA(accB[0], pB1, o0.x); F2_FMA(accB[1], pB1, o0.y);
            F2_FMA(accB[2], pB1, o1.x); F2_FMA(accB[3], pB1, o1.y);
        }
        __syncthreads();
    }
    u64* PA = (u64*)(g_PACC + (size_t)ks*M_TOK*DM + (size_t)m0*DM + h*HD);
    PA[0]=accA[0]; PA[1]=accA[1]; PA[2]=accA[2]; PA[3]=accA[3];
    u64* PB = (u64*)(g_PACC + (size_t)ks*M_TOK*DM + (size_t)m1*DM + h*HD);
    PB[0]=accB[0]; PB[1]=accB[1]; PB[2]=accB[2]; PB[3]=accB[3];
    unsigned slo, shi;
    UNPACK2(slo, shi, ssA);
    g_PSUM[ks*NH*M_TOK + h*M_TOK + m0] = __uint_as_float(slo) + __uint_as_float(shi);
    UNPACK2(slo, shi, ssB);
    g_PSUM[ks*NH*M_TOK + h*M_TOK + m1] = __uint_as_float(slo) + __uint_as_float(shi);
}

// ---------------- Gaussian-kernel gram sums (f32x2 dots; symmetric tile skip) ----
template<int KD, int SYM>
__device__ __forceinline__ u64 mmd_tile(const float (*Asm)[68], const float (*Bsm)[68],
                                        const float* na, const float* nb,
                                        int rbase, int ja, int ibase, int jbase,
                                        const ExpC& C)
{
    u64 acc2[4][4] = {};
    #pragma unroll
    for (int k = 0; k < KD; k += 4){
        ulonglong2 a0 = *(const ulonglong2*)&Asm[rbase+0][k];
        ulonglong2 a1 = *(const ulonglong2*)&Asm[rbase+1][k];
        ulonglong2 a2 = *(const ulonglong2*)&Asm[rbase+2][k];
        ulonglong2 a3 = *(const ulonglong2*)&Asm[rbase+3][k];
        ulonglong2 b0 = *(const ulonglong2*)&Bsm[ja    ][k];
        ulonglong2 b1 = *(const ulonglong2*)&Bsm[ja+32 ][k];
        ulonglong2 b2 = *(const ulonglong2*)&Bsm[ja+64 ][k];
        ulonglong2 b3 = *(const ulonglong2*)&Bsm[ja+96 ][k];
        F2_FMA(acc2[0][0], a0.x, b0.x); F2_FMA(acc2[0][0], a0.y, b0.y);
        F2_FMA(acc2[0][1], a0.x, b1.x); F2_FMA(acc2[0][1], a0.y, b1.y);
        F2_FMA(acc2[0][2], a0.x, b2.x); F2_FMA(acc2[0][2], a0.y, b2.y);
        F2_FMA(acc2[0][3], a0.x, b3.x); F2_FMA(acc2[0][3], a0.y, b3.y);
        F2_FMA(acc2[1][0], a1.x, b0.x); F2_FMA(acc2[1][0], a1.y, b0.y);
        F2_FMA(acc2[1][1], a1.x, b1.x); F2_FMA(acc2[1][1], a1.y, b1.y);
        F2_FMA(acc2[1][2], a1.x, b2.x); F2_FMA(acc2[1][2], a1.y, b2.y);
        F2_FMA(acc2[1][3], a1.x, b3.x); F2_FMA(acc2[1][3], a1.y, b3.y);
        F2_FMA(acc2[2][0], a2.x, b0.x); F2_FMA(acc2[2][0], a2.y, b0.y);
        F2_FMA(acc2[2][1], a2.x, b1.x); F2_FMA(acc2[2][1], a2.y, b1.y);
        F2_FMA(acc2[2][2], a2.x, b2.x); F2_FMA(acc2[2][2], a2.y, b2.y);
        F2_FMA(acc2[2][3], a2.x, b3.x); F2_FMA(acc2[2][3], a2.y, b3.y);
        F2_FMA(acc2[3][0], a3.x, b0.x); F2_FMA(acc2[3][0], a3.y, b0.y);
        F2_FMA(acc2[3][1], a3.x, b1.x); F2_FMA(acc2[3][1], a3.y, b1.y);
        F2_FMA(acc2[3][2], a3.x, b2.x); F2_FMA(acc2[3][2], a3.y, b2.y);
        F2_FMA(acc2[3][3], a3.x, b3.x); F2_FMA(acc2[3][3], a3.y, b3.y);
    }
    u64 psum2 = 0;
    #pragma unroll
    for (int i = 0; i < 4; i++){
        float nai = na[rbase+i];
        float x[4];
        #pragma unroll
        for (int u = 0; u < 4; u++){
            unsigned lo, hi; UNPACK2(lo, hi, acc2[i][u]);
            float dot = __uint_as_float(lo) + __uint_as_float(hi);
            float d = nai + nb[ja + 32*u] - 2.f*dot;
            x[u] = fminf(d, 150.f) * -0.5f;
            if (SYM){
                if (jbase + 32*u <= ibase + i) x[u] = -85.f;   // exp -> ~1e-37
            }
        }
        u64 s01, s23;
        PACK2(s01, __float_as_uint(x[0]), __float_as_uint(x[1]));
        PACK2(s23, __float_as_uint(x[2]), __float_as_uint(x[3]));
        unsigned d0, d1;
        u64 p01 = pexp2(s01, C, d0, d1);
        u64 p23 = pexp2(s23, C, d0, d1);
        F2_ADD(psum2, psum2, p01);
        F2_ADD(psum2, psum2, p23);
    }
    return psum2;
}

__global__ __launch_bounds__(256) void k_mmd(const float* __restrict__ XP,
                                             const float* __restrict__ RGB)
{
    __shared__ __align__(16) float Asm[32][68];
    __shared__ __align__(16) float Bsm[128][68];
    __shared__ float na[32], nb[128], red[256];
    const int type = blockIdx.y;
    const float *A, *B, *NA, *NB;
    if (type == 0){ A = XP;  B = XP;  NA = g_NX; NB = g_NX; }
    else if (type == 1){ A = RGB; B = RGB; NA = g_NY; NB = g_NY; }
    else { A = XP; B = RGB; NA = g_NX; NB = g_NY; }
    const int kd  = (type == 1) ? 64 : g_kd;
    const int sym = (type != 2);
    const ExpC C = make_expc();

    const int tid = threadIdx.x;
    const int ib  = blockIdx.x * 32;
    for (int idx = tid; idx < 512; idx += 256){
        int r = idx >> 4, kq = idx & 15;
        *(float4*)&Asm[r][kq*4] = ((const float4*)A)[(ib + r)*16 + kq];
    }
    if (tid < 32) na[tid] = NA[ib + tid];

    const int ja = tid & 31, rbase = (tid >> 5) * 4;
    const int ibase = ib + rbase;
    u64 psum2 = 0;
    for (int jt = 0; jt < 32; jt++){
        if (sym && jt*128 + 127 <= ib) continue;   // block-uniform: whole tile below diag
        __syncthreads();
        for (int idx = tid; idx < 2048; idx += 256){
            int r = idx >> 4, kq = idx & 15;
            *(float4*)&Bsm[r][kq*4] = ((const float4*)B)[(jt*128 + r)*16 + kq];
        }
        if (tid < 128) nb[tid] = NB[jt*128 + tid];
        __syncthreads();
        const int jbase = jt*128 + ja;
        u64 t;
        if (sym){
            if (kd == 32) t = mmd_tile<32,1>(Asm, Bsm, na, nb, rbase, ja, ibase, jbase, C);
            else          t = mmd_tile<64,1>(Asm, Bsm, na, nb, rbase, ja, ibase, jbase, C);
        } else {
            if (kd == 32) t = mmd_tile<32,0>(Asm, Bsm, na, nb, rbase, ja, ibase, jbase, C);
            else          t = mmd_tile<64,0>(Asm, Bsm, na, nb, rbase, ja, ibase, jbase, C);
        }
        F2_ADD(psum2, psum2, t);
    }
    unsigned lo, hi; UNPACK2(lo, hi, psum2);
    red[tid] = __uint_as_float(lo) + __uint_as_float(hi);
    __syncthreads();
    for (int s = 128; s > 0; s >>= 1){
        if (tid < s) red[tid] += red[tid + s];
        __syncthreads();
    }
    if (tid == 0) g_PART[type*128 + blockIdx.x] = red[0];
}

__global__ void k_final(float* __restrict__ dout, int out_size)
{
    int tid = threadIdx.x;  // 32
    float s[3];
    #pragma unroll
    for (int t = 0; t < 3; t++){
        float v = 0.f;
        for (int i = tid; i < 128; i += 32) v += g_PART[t*128 + i];
        #pragma unroll
        for (int off = 16; off > 0; off >>= 1) v += __shfl_xor_sync(0xffffffffu, v, off);
        s[t] = v;
    }
    if (tid == 0 && out_size > M_TOK*DM){
        // xx and yy were computed over strict-upper pairs: full = 2*S + 4096 (diag)
        const float inv = 1.f / 16777216.f;   // 1/(4096*4096)
        float s0 = 2.f*s[0] + 4096.f;
        float s1 = 2.f*s[1] + 4096.f;
        dout[M_TOK*DM] = (s0 + s1 - 2.f*s[2]) * inv;
    }
}

// ---------------- host orchestration --------------------------------------------
extern "C" void kernel_launch(void* const* d_in, const int* in_sizes, int n_in,
                              void* d_out, int out_size)
{
    (void)in_sizes; (void)n_in;
    const float* hsi  = (const float*)d_in[0];
    const float* rgb  = (const float*)d_in[1];
    const float* in_w = (const float*)d_in[2];
    const float* in_b = (const float*)d_in[3];
    const float* ow   = (const float*)d_in[4];
    const float* ob   = (const float*)d_in[5];
    const float* l1w  = (const float*)d_in[6];
    const float* l1b  = (const float*)d_in[7];
    const float* l2w  = (const float*)d_in[8];
    const float* l2b  = (const float*)d_in[9];
    const float* n1w  = (const float*)d_in[10];
    const float* n1b  = (const float*)d_in[11];
    const float* n2w  = (const float*)d_in[12];
    const float* n2b  = (const float*)d_in[13];
    const float* mask = (const float*)d_in[14];
    float* dout = (float*)d_out;

    float *pX, *pQKV, *pF1;
    cudaGetSymbolAddress((void**)&pX,   g_X);
    cudaGetSymbolAddress((void**)&pQKV, g_QKV);
    cudaGetSymbolAddress((void**)&pF1,  g_F1);

    for (int l = 0; l < NLAYER; l++){
        const float* Xin = (l == 0) ? hsi : pX;
        // QKV projection (q pre-scaled), scattered to [3][NH][M][HD]
        k_gemm<64,0,0><<<dim3(512,3), 256>>>(Xin, in_w + l*192*64, in_b + l*192,
                                             nullptr, nullptr, nullptr, pQKV, 0,
                                             nullptr, nullptr);
        // attention (4-way split-K additive softmax, 2 queries/thread)
        k_attn<<<dim3(16, NH, KSPLIT), 128>>>(pQKV);
        // out-proj (A = fused split-K combine) + residual + LN1
        k_gemm<64,2,1><<<dim3(512,1), 256>>>(nullptr, ow + l*64*64, ob + l*64,
                                             Xin, n1w + l*64, n1b + l*64, pX, 64,
                                             nullptr, nullptr);
        // FF1 (ReLU)
        k_gemm<64,1,0><<<dim3(512,4), 256>>>(pX, l1w + l*256*64, l1b + l*256,
                                             nullptr, nullptr, nullptr, pF1, 256,
                                             nullptr, nullptr);
        // FF2 + residual + LN2 (+ on last layer: prune, output, norms, kd)
        if (l < NLAYER-1){
            k_gemm<256,2,0><<<dim3(512,1), 256>>>(pF1, l2w + l*64*256, l2b + l*64,
                                                  pX, n2w + l*64, n2b + l*64, pX, 64,
                                                  nullptr, nullptr);
        } else {
            k_gemm<256,4,0><<<dim3(512,1), 256>>>(pF1, l2w + l*64*256, l2b + l*64,
                                                  pX, n2w + l*64, n2b + l*64, dout, 64,
                                                  mask, rgb);
        }
    }
    // MMD gram sums (xx, yy strict-upper; xy full), reading pruned x from dout
    k_mmd<<<dim3(128,3), 256>>>(dout, rgb);
    k_final<<<1, 32>>>(dout, out_size);
}

// round 11
// speedup vs baseline: 1.0498x; 1.0498x over previous
#include <cuda_runtime.h>

#define M_TOK 4096
#define DM    64
#define NH    8
#define HD    8
#define DFF   256
#define NLAYER 4
#define KSPLIT 4
#define GRID  256

typedef unsigned long long u64;

// ---------------- scratch (device globals; no allocation allowed) ----------------
__device__ unsigned g_barcnt;
__device__ int      g_work;
__device__ __align__(16) float g_X   [M_TOK*DM];
__device__ __align__(16) float g_QKV [3*NH*M_TOK*HD];
__device__ __align__(16) float g_F1  [M_TOK*DFF];
__device__ __align__(16) float g_PACC[KSPLIT*M_TOK*DM];
__device__ __align__(16) float g_PSUM[KSPLIT*NH*M_TOK];
__device__ float g_NX[M_TOK];
__device__ float g_NY[M_TOK];
__device__ float g_PART[3*128];
__device__ int   g_kd;

// ---------------- packed f32x2 helpers (SASS FFMA2: only reachable via PTX) ------
#define F2_FMA3(d,a,b,c) asm("fma.rn.f32x2 %0,%1,%2,%3;" : "=l"(d) : "l"(a),"l"(b),"l"(c))
#define F2_FMA(d,a,b)    asm("fma.rn.f32x2 %0,%1,%2,%0;" : "+l"(d) : "l"(a),"l"(b))
#define F2_HORN(p,f,c)   asm("fma.rn.f32x2 %0,%0,%1,%2;" : "+l"(p) : "l"(f),"l"(c))
#define F2_MUL(d,a,b)    asm("mul.rn.f32x2 %0,%1,%2;"    : "=l"(d) : "l"(a),"l"(b))
#define F2_ADD(d,a,b)    asm("add.rn.f32x2 %0,%1,%2;"    : "+l"(d) : "l"(a),"l"(b))
#define PACK2(d,lo,hi)   asm("mov.b64 %0,{%1,%2};" : "=l"(d) : "r"(lo),"r"(hi))
#define UNPACK2(lo,hi,s) asm("mov.b64 {%0,%1},%2;" : "=r"(lo),"=r"(hi) : "l"(s))

__device__ __forceinline__ u64 pairbits(unsigned x){
    u64 r; asm("mov.b64 %0,{%1,%1};" : "=l"(r) : "r"(x)); return r;
}

struct ExpC { u64 L2E, MAG, N1, c5, c4, c3, c2, c1, c0; };
__device__ __forceinline__ ExpC make_expc(){
    ExpC e;
    e.L2E = pairbits(0x3FB8AA3Bu);
    e.MAG = pairbits(0x4B400000u);
    e.N1  = pairbits(0xBF800000u);
    e.c5  = pairbits(__float_as_uint(1.3333558146e-3f));
    e.c4  = pairbits(__float_as_uint(9.618129107e-3f));
    e.c3  = pairbits(__float_as_uint(5.550410866e-2f));
    e.c2  = pairbits(__float_as_uint(2.402264923e-1f));
    e.c1  = pairbits(__float_as_uint(6.9314718056e-1f));
    e.c0  = pairbits(0x3F800000u);
    return e;
}

__device__ __forceinline__ u64 pexp2(u64 s, const ExpC& C, unsigned& r0, unsigned& r1){
    u64 t, nfn, f, p;
    F2_FMA3(t,   s, C.L2E, C.MAG);
    F2_FMA3(nfn, t, C.N1,  C.MAG);
    F2_FMA3(f,   s, C.L2E, nfn);
    F2_FMA3(p, C.c5, f, C.c4);
    F2_HORN(p, f, C.c3);
    F2_HORN(p, f, C.c2);
    F2_HORN(p, f, C.c1);
    F2_HORN(p, f, C.c0);
    unsigned t0,t1,p0,p1;
    UNPACK2(t0,t1,t); UNPACK2(p0,p1,p);
    r0 = p0 + (t0 << 23);
    r1 = p1 + (t1 << 23);
    u64 r; PACK2(r, r0, r1);
    return r;
}

// ---------------- shared memory union (45.2 KB -> 2 CTAs/SM guaranteed) ----------
struct GemmS { float A[16][68]; float W[64][66]; };
struct AttnS { float Kp[4096]; float4 Vs[1024]; };
struct MmdS  { float A[32][68]; float B[128][68]; float na[32]; float nb[128]; float red[256]; };
union SmemU { GemmS g; AttnS a; MmdS m; };

// ---------------- grid barrier (monotonic counter; all 256 CTAs co-resident) -----
__device__ __forceinline__ void gridbar(unsigned& phase){
    __syncthreads();
    phase += 1;
    if (threadIdx.x == 0){
        __threadfence();
        atomicAdd(&g_barcnt, 1u);
        while (atomicAdd(&g_barcnt, 0u) < phase*GRID) {}
        __threadfence();
    }
    __syncthreads();
}

// ---------------- 16-row GEMM tile: C[rb..rb+16, cb..cb+64] = A @ W^T + b --------
// ASRC 0: A from global (lda = KDIM); ASRC 1: A = split-K attention combine.
// EPI 0: scatter to Q/K/V head layout (q scaled); EPI 1: ReLU; EPI 2: +res, LN;
// EPI 4: +res, LN, *mask -> OUT(dout), row norms NX/NY.
template<int KDIM, int EPI, int ASRC>
__device__ __forceinline__ void gemm16(
    GemmS& S, int rb, int cb, int slice,
    const float* __restrict__ A,
    const float* __restrict__ W,
    const float* __restrict__ bias,
    const float* __restrict__ RES,
    const float* __restrict__ lnw, const float* __restrict__ lnb,
    float* __restrict__ OUT, int ldo,
    const float* __restrict__ mask, const float* __restrict__ RGB)
{
    const int tid = threadIdx.x;
    const int c0  = tid & 31;
    const int rbase = (tid >> 5) * 2;
    u64 acc2[2][2] = {};

    __syncthreads();   // protect smem reuse from previous stage's reads
    #pragma unroll
    for (int ch = 0; ch < KDIM/64; ch++){
        {
            int r = tid >> 4, kq = tid & 15;     // 256 float4s, one per thread
            float4 v;
            if (ASRC == 0){
                v = ((const float4*)(A + (size_t)(rb + r)*KDIM + ch*64))[kq];
            } else {
                int m = rb + r;
                float4 a0 = *(const float4*)&g_PACC[(size_t)(0*M_TOK + m)*DM + kq*4];
                float4 a1 = *(const float4*)&g_PACC[(size_t)(1*M_TOK + m)*DM + kq*4];
                float4 a2 = *(const float4*)&g_PACC[(size_t)(2*M_TOK + m)*DM + kq*4];
                float4 a3 = *(const float4*)&g_PACC[(size_t)(3*M_TOK + m)*DM + kq*4];
                int h = kq >> 1;
                float s = g_PSUM[0*NH*M_TOK + h*M_TOK + m]
                        + g_PSUM[1*NH*M_TOK + h*M_TOK + m]
                        + g_PSUM[2*NH*M_TOK + h*M_TOK + m]
                        + g_PSUM[3*NH*M_TOK + h*M_TOK + m];
                float inv = 1.f / s;
                v.x = (a0.x+a1.x+a2.x+a3.x)*inv;
                v.y = (a0.y+a1.y+a2.y+a3.y)*inv;
                v.z = (a0.z+a1.z+a2.z+a3.z)*inv;
                v.w = (a0.w+a1.w+a2.w+a3.w)*inv;
            }
            *(float4*)&S.A[r][kq*4] = v;
        }
        #pragma unroll
        for (int idx = tid; idx < 4096; idx += 256){
            int c = idx >> 6, k = idx & 63;
            S.W[c][k] = W[(size_t)(cb + c)*KDIM + ch*64 + k];
        }
        __syncthreads();
        #pragma unroll
        for (int k = 0; k < 64; k += 4){
            ulonglong2 a0 = *(const ulonglong2*)&S.A[rbase+0][k];
            ulonglong2 a1 = *(const ulonglong2*)&S.A[rbase+1][k];
            u64 w0a = *(const u64*)&S.W[c0   ][k];
            u64 w0b = *(const u64*)&S.W[c0   ][k+2];
            u64 w1a = *(const u64*)&S.W[c0+32][k];
            u64 w1b = *(const u64*)&S.W[c0+32][k+2];
            F2_FMA(acc2[0][0], a0.x, w0a); F2_FMA(acc2[0][0], a0.y, w0b);
            F2_FMA(acc2[0][1], a0.x, w1a); F2_FMA(acc2[0][1], a0.y, w1b);
            F2_FMA(acc2[1][0], a1.x, w0a); F2_FMA(acc2[1][0], a1.y, w0b);
            F2_FMA(acc2[1][1], a1.x, w1a); F2_FMA(acc2[1][1], a1.y, w1b);
        }
        __syncthreads();
    }

    const float qs = (EPI == 0 && slice == 0) ? 0.35355339059327373f : 1.0f;
    #pragma unroll
    for (int i = 0; i < 2; i++){
        int m = rb + rbase + i;
        #pragma unroll
        for (int u = 0; u < 2; u++){
            int c = c0 + 32*u;
            unsigned lo, hi;
            UNPACK2(lo, hi, acc2[i][u]);
            float v = __uint_as_float(lo) + __uint_as_float(hi) + bias[cb + c];
            if (EPI == 0){
                v *= qs;
                OUT[((slice*NH + (c >> 3))*M_TOK + m)*HD + (c & 7)] = v;
            } else if (EPI == 1){
                OUT[(size_t)m*ldo + cb + c] = fmaxf(v, 0.f);
            } else {
                S.A[rbase+i][c] = v + RES[m*DM + c];
            }
        }
    }
    if (EPI >= 2){
        __syncthreads();
        int row = tid >> 4, seg = tid & 15;
        float s = 0.f, s2 = 0.f;
        #pragma unroll
        for (int t = 0; t < 4; t++){
            float x = S.A[row][seg*4 + t];
            s += x; s2 = fmaf(x, x, s2);
        }
        #pragma unroll
        for (int off = 8; off > 0; off >>= 1){
            s  += __shfl_xor_sync(0xffffffffu, s,  off);
            s2 += __shfl_xor_sync(0xffffffffu, s2, off);
        }
        float mean = s * (1.f/64.f);
        float var  = fmaf(-mean, mean, s2 * (1.f/64.f));
        float rstd = rsqrtf(var + 1e-5f);
        int m = rb + row;
        if (EPI == 2){
            #pragma unroll
            for (int t = 0; t < 4; t++){
                int c = seg*4 + t;
                OUT[m*DM + c] = (S.A[row][c] - mean) * rstd * lnw[c] + lnb[c];
            }
        } else {   // EPI 4: prune, emit output, row norms
            float nx = 0.f, ny = 0.f;
            #pragma unroll
            for (int t = 0; t < 4; t++){
                int c = seg*4 + t;
                float o  = (S.A[row][c] - mean) * rstd * lnw[c] + lnb[c];
                float xv = o * mask[c];
                OUT[m*DM + c] = xv;
                float yv = RGB[m*DM + c];
                nx = fmaf(xv, xv, nx);
                ny = fmaf(yv, yv, ny);
            }
            #pragma unroll
            for (int off = 8; off > 0; off >>= 1){
                nx += __shfl_xor_sync(0xffffffffu, nx, off);
                ny += __shfl_xor_sync(0xffffffffu, ny, off);
            }
            if (seg == 0){ g_NX[m] = nx; g_NY[m] = ny; }
        }
    }
}

// ---------------- attention unit: 512 queries x 1 head x 1024 keys ---------------
__device__ __forceinline__ void attn_unit(AttnS& S, const float* __restrict__ QKV, int u)
{
    const int tid = threadIdx.x;
    const int mb = u & 7, h = (u >> 3) & 7, ks = u >> 6;
    const int m0 = mb*512 + tid, m1 = m0 + 256;
    const float4* Qb = (const float4*)QKV;
    const float4* K4 = (const float4*)QKV + (size_t)(NH*M_TOK + h*M_TOK)*2;
    const float4* V4 = (const float4*)QKV + (size_t)(2*NH*M_TOK + h*M_TOK)*2;

    const ExpC C = make_expc();
    float4 qa0 = Qb[(size_t)(h*M_TOK + m0)*2], qa1 = Qb[(size_t)(h*M_TOK + m0)*2 + 1];
    float4 qb0 = Qb[(size_t)(h*M_TOK + m1)*2], qb1 = Qb[(size_t)(h*M_TOK + m1)*2 + 1];
    u64 qA[8], qB[8];
    qA[0]=pairbits(__float_as_uint(qa0.x)); qA[1]=pairbits(__float_as_uint(qa0.y));
    qA[2]=pairbits(__float_as_uint(qa0.z)); qA[3]=pairbits(__float_as_uint(qa0.w));
    qA[4]=pairbits(__float_as_uint(qa1.x)); qA[5]=pairbits(__float_as_uint(qa1.y));
    qA[6]=pairbits(__float_as_uint(qa1.z)); qA[7]=pairbits(__float_as_uint(qa1.w));
    qB[0]=pairbits(__float_as_uint(qb0.x)); qB[1]=pairbits(__float_as_uint(qb0.y));
    qB[2]=pairbits(__float_as_uint(qb0.z)); qB[3]=pairbits(__float_as_uint(qb0.w));
    qB[4]=pairbits(__float_as_uint(qb1.x)); qB[5]=pairbits(__float_as_uint(qb1.y));
    qB[6]=pairbits(__float_as_uint(qb1.z)); qB[7]=pairbits(__float_as_uint(qb1.w));

    u64 accA[4] = {0,0,0,0}, accB[4] = {0,0,0,0};
    u64 ssA = 0, ssB = 0;

    __syncthreads();
    for (int kt = 0; kt < 2; kt++){
        int key0 = ks*1024 + kt*512;
        for (int idx = tid; idx < 1024; idx += 256){
            int j = idx >> 1, hf = idx & 1;
            float4 kv = K4[key0*2 + idx];
            float* dst = S.Kp + (j>>1)*16 + hf*8 + (j&1);
            dst[0]=kv.x; dst[2]=kv.y; dst[4]=kv.z; dst[6]=kv.w;
            S.Vs[idx] = V4[key0*2 + idx];
        }
        __syncthreads();
        const ulonglong2* vr = (const ulonglong2*)S.Vs;
        #pragma unroll 2
        for (int jp = 0; jp < 256; jp++){
            const ulonglong2* kr = (const ulonglong2*)(S.Kp + jp*16);
            ulonglong2 k01 = kr[0], k23 = kr[1], k45 = kr[2], k67 = kr[3];
            u64 sA, sB;
            F2_MUL(sA, qA[0], k01.x);
            F2_FMA(sA, qA[1], k01.y); F2_FMA(sA, qA[2], k23.x); F2_FMA(sA, qA[3], k23.y);
            F2_FMA(sA, qA[4], k45.x); F2_FMA(sA, qA[5], k45.y);
            F2_FMA(sA, qA[6], k67.x); F2_FMA(sA, qA[7], k67.y);
            F2_MUL(sB, qB[0], k01.x);
            F2_FMA(sB, qB[1], k01.y); F2_FMA(sB, qB[2], k23.x); F2_FMA(sB, qB[3], k23.y);
            F2_FMA(sB, qB[4], k45.x); F2_FMA(sB, qB[5], k45.y);
            F2_FMA(sB, qB[6], k67.x); F2_FMA(sB, qB[7], k67.y);
            unsigned a0r, a1r, b0r, b1r;
            u64 pA = pexp2(sA, C, a0r, a1r);
            u64 pB = pexp2(sB, C, b0r, b1r);
            F2_ADD(ssA, ssA, pA);
            F2_ADD(ssB, ssB, pB);
            u64 pA0 = pairbits(a0r), pA1 = pairbits(a1r);
            u64 pB0 = pairbits(b0r), pB1 = pairbits(b1r);
            ulonglong2 e0 = vr[4*jp],   e1 = vr[4*jp+1];
            ulonglong2 o0 = vr[4*jp+2], o1 = vr[4*jp+3];
            F2_FMA(accA[0], pA0, e0.x); F2_FMA(accA[1], pA0, e0.y);
            F2_FMA(accA[2], pA0, e1.x); F2_FMA(accA[3], pA0, e1.y);
            F2_FMA(accA[0], pA1, o0.x); F2_FMA(accA[1], pA1, o0.y);
            F2_FMA(accA[2], pA1, o1.x); F2_FMA(accA[3], pA1, o1.y);
            F2_FMA(accB[0], pB0, e0.x); F2_FMA(accB[1], pB0, e0.y);
            F2_FMA(accB[2], pB0, e1.x); F2_FMA(accB[3], pB0, e1.y);
            F2_FMA(accB[0], pB1, o0.x); F2_FMA(accB[1], pB1, o0.y);
            F2_FMA(accB[2], pB1, o1.x); F2_FMA(accB[3], pB1, o1.y);
        }
        __syncthreads();
    }
    u64* PA = (u64*)(g_PACC + (size_t)ks*M_TOK*DM + (size_t)m0*DM + h*HD);
    PA[0]=accA[0]; PA[1]=accA[1]; PA[2]=accA[2]; PA[3]=accA[3];
    u64* PB = (u64*)(g_PACC + (size_t)ks*M_TOK*DM + (size_t)m1*DM + h*HD);
    PB[0]=accB[0]; PB[1]=accB[1]; PB[2]=accB[2]; PB[3]=accB[3];
    unsigned slo, shi;
    UNPACK2(slo, shi, ssA);
    g_PSUM[ks*NH*M_TOK + h*M_TOK + m0] = __uint_as_float(slo) + __uint_as_float(shi);
    UNPACK2(slo, shi, ssB);
    g_PSUM[ks*NH*M_TOK + h*M_TOK + m1] = __uint_as_float(slo) + __uint_as_float(shi);
}

// ---------------- Gaussian-kernel gram sums (f32x2; symmetric tile skip) ---------
template<int KD, int SYM>
__device__ __forceinline__ u64 mmd_tile(const float (*Asm)[68], const float (*Bsm)[68],
                                        const float* na, const float* nb,
                                        int rbase, int ja, int ibase, int jbase,
                                        const ExpC& C)
{
    u64 acc2[4][4] = {};
    #pragma unroll
    for (int k = 0; k < KD; k += 4){
        ulonglong2 a0 = *(const ulonglong2*)&Asm[rbase+0][k];
        ulonglong2 a1 = *(const ulonglong2*)&Asm[rbase+1][k];
        ulonglong2 a2 = *(const ulonglong2*)&Asm[rbase+2][k];
        ulonglong2 a3 = *(const ulonglong2*)&Asm[rbase+3][k];
        ulonglong2 b0 = *(const ulonglong2*)&Bsm[ja    ][k];
        ulonglong2 b1 = *(const ulonglong2*)&Bsm[ja+32 ][k];
        ulonglong2 b2 = *(const ulonglong2*)&Bsm[ja+64 ][k];
        ulonglong2 b3 = *(const ulonglong2*)&Bsm[ja+96 ][k];
        F2_FMA(acc2[0][0], a0.x, b0.x); F2_FMA(acc2[0][0], a0.y, b0.y);
        F2_FMA(acc2[0][1], a0.x, b1.x); F2_FMA(acc2[0][1], a0.y, b1.y);
        F2_FMA(acc2[0][2], a0.x, b2.x); F2_FMA(acc2[0][2], a0.y, b2.y);
        F2_FMA(acc2[0][3], a0.x, b3.x); F2_FMA(acc2[0][3], a0.y, b3.y);
        F2_FMA(acc2[1][0], a1.x, b0.x); F2_FMA(acc2[1][0], a1.y, b0.y);
        F2_FMA(acc2[1][1], a1.x, b1.x); F2_FMA(acc2[1][1], a1.y, b1.y);
        F2_FMA(acc2[1][2], a1.x, b2.x); F2_FMA(acc2[1][2], a1.y, b2.y);
        F2_FMA(acc2[1][3], a1.x, b3.x); F2_FMA(acc2[1][3], a1.y, b3.y);
        F2_FMA(acc2[2][0], a2.x, b0.x); F2_FMA(acc2[2][0], a2.y, b0.y);
        F2_FMA(acc2[2][1], a2.x, b1.x); F2_FMA(acc2[2][1], a2.y, b1.y);
        F2_FMA(acc2[2][2], a2.x, b2.x); F2_FMA(acc2[2][2], a2.y, b2.y);
        F2_FMA(acc2[2][3], a2.x, b3.x); F2_FMA(acc2[2][3], a2.y, b3.y);
        F2_FMA(acc2[3][0], a3.x, b0.x); F2_FMA(acc2[3][0], a3.y, b0.y);
        F2_FMA(acc2[3][1], a3.x, b1.x); F2_FMA(acc2[3][1], a3.y, b1.y);
        F2_FMA(acc2[3][2], a3.x, b2.x); F2_FMA(acc2[3][2], a3.y, b2.y);
        F2_FMA(acc2[3][3], a3.x, b3.x); F2_FMA(acc2[3][3], a3.y, b3.y);
    }
    u64 psum2 = 0;
    #pragma unroll
    for (int i = 0; i < 4; i++){
        float nai = na[rbase+i];
        float x[4];
        #pragma unroll
        for (int u = 0; u < 4; u++){
            unsigned lo, hi; UNPACK2(lo, hi, acc2[i][u]);
            float dot = __uint_as_float(lo) + __uint_as_float(hi);
            float d = nai + nb[ja + 32*u] - 2.f*dot;
            x[u] = fminf(d, 150.f) * -0.5f;
            if (SYM){
                if (jbase + 32*u <= ibase + i) x[u] = -85.f;
            }
        }
        u64 s01, s23;
        PACK2(s01, __float_as_uint(x[0]), __float_as_uint(x[1]));
        PACK2(s23, __float_as_uint(x[2]), __float_as_uint(x[3]));
        unsigned d0, d1;
        u64 p01 = pexp2(s01, C, d0, d1);
        u64 p23 = pexp2(s23, C, d0, d1);
        F2_ADD(psum2, psum2, p01);
        F2_ADD(psum2, psum2, p23);
    }
    return psum2;
}

__device__ __forceinline__ void mmd_unit(MmdS& S, int u,
                                         const float* __restrict__ XP,
                                         const float* __restrict__ RGB)
{
    const int type = u >> 7, ib4 = u & 127;
    const float *A, *B, *NA, *NB;
    if (type == 0){ A = XP;  B = XP;  NA = g_NX; NB = g_NX; }
    else if (type == 1){ A = RGB; B = RGB; NA = g_NY; NB = g_NY; }
    else { A = XP; B = RGB; NA = g_NX; NB = g_NY; }
    const int kd  = (type == 1) ? 64 : g_kd;
    const int sym = (type != 2);
    const ExpC C = make_expc();

    const int tid = threadIdx.x;
    const int ib  = ib4 * 32;
    for (int idx = tid; idx < 512; idx += 256){
        int r = idx >> 4, kq = idx & 15;
        *(float4*)&S.A[r][kq*4] = ((const float4*)A)[(ib + r)*16 + kq];
    }
    if (tid < 32) S.na[tid] = NA[ib + tid];

    const int ja = tid & 31, rbase = (tid >> 5) * 4;
    const int ibase = ib + rbase;
    u64 psum2 = 0;
    for (int jt = 0; jt < 32; jt++){
        if (sym && jt*128 + 127 <= ib) continue;
        __syncthreads();
        for (int idx = tid; idx < 2048; idx += 256){
            int r = idx >> 4, kq = idx & 15;
            *(float4*)&S.B[r][kq*4] = ((const float4*)B)[(jt*128 + r)*16 + kq];
        }
        if (tid < 128) S.nb[tid] = NB[jt*128 + tid];
        __syncthreads();
        const int jbase = jt*128 + ja;
        u64 t;
        if (sym){
            if (kd == 32) t = mmd_tile<32,1>(S.A, S.B, S.na, S.nb, rbase, ja, ibase, jbase, C);
            else          t = mmd_tile<64,1>(S.A, S.B, S.na, S.nb, rbase, ja, ibase, jbase, C);
        } else {
            if (kd == 32) t = mmd_tile<32,0>(S.A, S.B, S.na, S.nb, rbase, ja, ibase, jbase, C);
            else          t = mmd_tile<64,0>(S.A, S.B, S.na, S.nb, rbase, ja, ibase, jbase, C);
        }
        F2_ADD(psum2, psum2, t);
    }
    unsigned lo, hi; UNPACK2(lo, hi, psum2);
    __syncthreads();
    S.red[tid] = __uint_as_float(lo) + __uint_as_float(hi);
    __syncthreads();
    for (int s = 128; s > 0; s >>= 1){
        if (tid < s) S.red[tid] += S.red[tid + s];
        __syncthreads();
    }
    if (tid == 0) g_PART[type*128 + ib4] = S.red[0];
}

// ---------------- init + megakernel ----------------------------------------------
__global__ void k_init(){
    g_barcnt = 0;
    g_work = 0;
}

__global__ __launch_bounds__(256, 2) void k_mega(
    const float* __restrict__ hsi, const float* __restrict__ rgb,
    const float* __restrict__ in_w, const float* __restrict__ in_b,
    const float* __restrict__ ow,   const float* __restrict__ ob,
    const float* __restrict__ l1w,  const float* __restrict__ l1b,
    const float* __restrict__ l2w,  const float* __restrict__ l2b,
    const float* __restrict__ n1w,  const float* __restrict__ n1b,
    const float* __restrict__ n2w,  const float* __restrict__ n2b,
    const float* __restrict__ mask, float* __restrict__ dout, int out_size)
{
    __shared__ SmemU SM;
    __shared__ int s_u;
    const int cta = blockIdx.x, tid = threadIdx.x;
    const int rb = cta * 16;
    unsigned phase = 0;

    for (int l = 0; l < NLAYER; l++){
        const float* Xin = (l == 0) ? hsi : g_X;
        // QKV: 3 col-slices, q pre-scaled, head-layout scatter
        #pragma unroll
        for (int s = 0; s < 3; s++)
            gemm16<64,0,0>(SM.g, rb, s*64, s, Xin, in_w + l*192*64, in_b + l*192,
                           nullptr, nullptr, nullptr, g_QKV, 0, nullptr, nullptr);
        gridbar(phase);                      // attention reads all tokens' K/V
        // attention: unit = (mb, h, ks), one per CTA
        attn_unit(SM.a, g_QKV, cta);
        gridbar(phase);                      // proj combine reads cross-CTA PACC
        // out-proj (split-K combine as A) + residual + LN1
        gemm16<64,2,1>(SM.g, rb, 0, 0, nullptr, ow + l*64*64, ob + l*64,
                       Xin, n1w + l*64, n1b + l*64, g_X, 64, nullptr, nullptr);
        // FF1 (ReLU): 4 col-slices — row-aligned with proj, no barrier needed
        #pragma unroll
        for (int s = 0; s < 4; s++)
            gemm16<64,1,0>(SM.g, rb, s*64, 0, g_X, l1w + l*256*64, l1b + l*256,
                           nullptr, nullptr, nullptr, g_F1, 256, nullptr, nullptr);
        // FF2 + residual + LN2 (+ final layer: prune, output, norms) — row-aligned
        if (l < NLAYER-1){
            gemm16<256,2,0>(SM.g, rb, 0, 0, g_F1, l2w + l*64*256, l2b + l*64,
                            g_X, n2w + l*64, n2b + l*64, g_X, 64, nullptr, nullptr);
        } else {
            gemm16<256,4,0>(SM.g, rb, 0, 0, g_F1, l2w + l*64*256, l2b + l*64,
                            g_X, n2w + l*64, n2b + l*64, dout, 64, mask, rgb);
            if (cta == 0 && tid < 32){
                unsigned any = __ballot_sync(0xffffffffu, mask[32 + tid] != 0.f);
                if (tid == 0) g_kd = any ? 64 : 32;
            }
        }
    }
    gridbar(phase);                          // MMD reads all dout rows + norms + kd
    // MMD: atomic work queue over 384 units (deterministic: per-unit g_PART slot)
    for (;;){
        __syncthreads();
        if (tid == 0) s_u = atomicAdd(&g_work, 1);
        __syncthreads();
        int u = s_u;
        if (u >= 384) break;
        mmd_unit(SM.m, u, dout, rgb);
    }
    gridbar(phase);                          // final reduce reads all g_PART
    if (cta == 0 && tid < 32){
        float s[3];
        #pragma unroll
        for (int t = 0; t < 3; t++){
            float v = 0.f;
            for (int i = tid; i < 128; i += 32) v += g_PART[t*128 + i];
            #pragma unroll
            for (int off = 16; off > 0; off >>= 1) v += __shfl_xor_sync(0xffffffffu, v, off);
            s[t] = v;
        }
        if (tid == 0 && out_size > M_TOK*DM){
            const float inv = 1.f / 16777216.f;   // 1/(4096*4096)
            float s0 = 2.f*s[0] + 4096.f;         // strict-upper -> full (sym + diag)
            float s1 = 2.f*s[1] + 4096.f;
            dout[M_TOK*DM] = (s0 + s1 - 2.f*s[2]) * inv;
        }
    }
}

// ---------------- host orchestration ---------------------------------------------
extern "C" void kernel_launch(void* const* d_in, const int* in_sizes, int n_in,
                              void* d_out, int out_size)
{
    (void)in_sizes; (void)n_in;
    const float* hsi  = (const float*)d_in[0];
    const float* rgb  = (const float*)d_in[1];
    const float* in_w = (const float*)d_in[2];
    const float* in_b = (const float*)d_in[3];
    const float* ow   = (const float*)d_in[4];
    const float* ob   = (const float*)d_in[5];
    const float* l1w  = (const float*)d_in[6];
    const float* l1b  = (const float*)d_in[7];
    const float* l2w  = (const float*)d_in[8];
    const float* l2b  = (const float*)d_in[9];
    const float* n1w  = (const float*)d_in[10];
    const float* n1b  = (const float*)d_in[11];
    const float* n2w  = (const float*)d_in[12];
    const float* n2b  = (const float*)d_in[13];
    const float* mask = (const float*)d_in[14];
    float* dout = (float*)d_out;

    k_init<<<1, 1>>>();
    k_mega<<<GRID, 256>>>(hsi, rgb, in_w, in_b, ow, ob, l1w, l1b, l2w, l2b,
                          n1w, n1b, n2w, n2b, mask, dout, out_size);
}

// round 14
// speedup vs baseline: 1.1180x; 1.0650x over previous
#include <cuda_runtime.h>

#define M_TOK 4096
#define DM    64
#define NH    8
#define HD    8
#define DFF   256
#define NLAYER 4
#define KSPLIT 4
#define GRID  256

typedef unsigned long long u64;

// ---------------- scratch (device globals; no allocation allowed) ----------------
__device__ unsigned g_barcnt;
__device__ int      g_work;
__device__ __align__(16) float g_X   [M_TOK*DM];
__device__ __align__(16) float g_QKV [3*NH*M_TOK*HD];
__device__ __align__(16) float g_F1  [M_TOK*DFF];
__device__ __align__(16) float g_PACC[KSPLIT*M_TOK*DM];
__device__ __align__(16) float g_PSUM[KSPLIT*NH*M_TOK];
__device__ float g_NX[M_TOK];
__device__ float g_NY[M_TOK];
__device__ float g_PART[3*128];
__device__ int   g_kd;

// ---------------- packed f32x2 helpers (SASS FFMA2: only reachable via PTX) ------
#define F2_FMA3(d,a,b,c) asm("fma.rn.f32x2 %0,%1,%2,%3;" : "=l"(d) : "l"(a),"l"(b),"l"(c))
#define F2_FMA(d,a,b)    asm("fma.rn.f32x2 %0,%1,%2,%0;" : "+l"(d) : "l"(a),"l"(b))
#define F2_HORN(p,f,c)   asm("fma.rn.f32x2 %0,%0,%1,%2;" : "+l"(p) : "l"(f),"l"(c))
#define F2_MUL(d,a,b)    asm("mul.rn.f32x2 %0,%1,%2;"    : "=l"(d) : "l"(a),"l"(b))
#define F2_ADD(d,a,b)    asm("add.rn.f32x2 %0,%1,%2;"    : "+l"(d) : "l"(a),"l"(b))
#define PACK2(d,lo,hi)   asm("mov.b64 %0,{%1,%2};" : "=l"(d) : "r"(lo),"r"(hi))
#define UNPACK2(lo,hi,s) asm("mov.b64 {%0,%1},%2;" : "=r"(lo),"=r"(hi) : "l"(s))

__device__ __forceinline__ u64 pairbits(unsigned x){
    u64 r; asm("mov.b64 %0,{%1,%1};" : "=l"(r) : "r"(x)); return r;
}

// Degree-4 polynomial exp (err ~3e-5 rel — 30x under threshold, saves 1 FMA + chain)
struct ExpC { u64 L2E, MAG, N1, c4, c3, c2, c1, c0; };
__device__ __forceinline__ ExpC make_expc(){
    ExpC e;
    e.L2E = pairbits(0x3FB8AA3Bu);          // log2(e)
    e.MAG = pairbits(0x4B400000u);          // 12582912.f
    e.N1  = pairbits(0xBF800000u);          // -1.f
    e.c4  = pairbits(__float_as_uint(9.618129107e-3f));
    e.c3  = pairbits(__float_as_uint(5.550410866e-2f));
    e.c2  = pairbits(__float_as_uint(2.402264923e-1f));
    e.c1  = pairbits(__float_as_uint(6.9314718056e-1f));
    e.c0  = pairbits(0x3F800000u);
    return e;
}

__device__ __forceinline__ u64 pexp2(u64 s, const ExpC& C, unsigned& r0, unsigned& r1){
    u64 t, nfn, f, p;
    F2_FMA3(t,   s, C.L2E, C.MAG);   // round(x*log2e) in mantissa
    F2_FMA3(nfn, t, C.N1,  C.MAG);   // magic - t = -fn
    F2_FMA3(f,   s, C.L2E, nfn);     // frac in [-0.5, 0.5]
    F2_FMA3(p, C.c4, f, C.c3);       // degree-4 Horner
    F2_HORN(p, f, C.c2);
    F2_HORN(p, f, C.c1);
    F2_HORN(p, f, C.c0);
    unsigned t0,t1,p0,p1;
    UNPACK2(t0,t1,t); UNPACK2(p0,p1,p);
    r0 = p0 + (t0 << 23);            // exponent splice: low 9 bits of magic are 0
    r1 = p1 + (t1 << 23);
    u64 r; PACK2(r, r0, r1);
    return r;
}

// ---------------- shared memory union (45.2 KB -> 2 CTAs/SM guaranteed) ----------
struct GemmS { float A[16][68]; float W[64][66]; };
struct AttnS { float Kp[4096]; float4 Vs[1024]; };
struct MmdS  { float A[32][68]; float B[128][68]; float na[32]; float nb[128]; float red[256]; };
union SmemU { GemmS g; AttnS a; MmdS m; };

// ---------------- grid barrier: release-arrive + acquire-load poll (no RMW spin) -
__device__ __forceinline__ void gridbar(unsigned& phase){
    __syncthreads();
    phase += 1;
    if (threadIdx.x == 0){
        __threadfence();                       // release
        atomicAdd(&g_barcnt, 1u);
        const unsigned target = phase*GRID;
        unsigned v;
        do {
            asm volatile("ld.global.acquire.gpu.u32 %0, [%1];"
                         : "=r"(v) : "l"(&g_barcnt));
        } while (v < target);
    }
    __syncthreads();
}

// ---------------- 16-row GEMM tile: C[rb..rb+16, cb..cb+64] = A @ W^T + b --------
// ASRC 0: A from global (lda = KDIM); ASRC 1: A = split-K attention combine.
// EPI 0: scatter to Q/K/V head layout (q scaled); EPI 1: ReLU; EPI 2: +res, LN;
// EPI 4: +res, LN, *mask -> OUT(dout), row norms NX/NY.
template<int KDIM, int EPI, int ASRC>
__device__ __forceinline__ void gemm16(
    GemmS& S, int rb, int cb, int slice,
    const float* __restrict__ A,
    const float* __restrict__ W,
    const float* __restrict__ bias,
    const float* __restrict__ RES,
    const float* __restrict__ lnw, const float* __restrict__ lnb,
    float* __restrict__ OUT, int ldo,
    const float* __restrict__ mask, const float* __restrict__ RGB)
{
    const int tid = threadIdx.x;
    const int c0  = tid & 31;
    const int rbase = (tid >> 5) * 2;
    u64 acc2[2][2] = {};

    __syncthreads();   // protect smem reuse from previous stage's reads
    #pragma unroll
    for (int ch = 0; ch < KDIM/64; ch++){
        {
            int r = tid >> 4, kq = tid & 15;     // 256 float4s, one per thread
            float4 v;
            if (ASRC == 0){
                v = ((const float4*)(A + (size_t)(rb + r)*KDIM + ch*64))[kq];
            } else {
                int m = rb + r;
                float4 a0 = *(const float4*)&g_PACC[(size_t)(0*M_TOK + m)*DM + kq*4];
                float4 a1 = *(const float4*)&g_PACC[(size_t)(1*M_TOK + m)*DM + kq*4];
                float4 a2 = *(const float4*)&g_PACC[(size_t)(2*M_TOK + m)*DM + kq*4];
                float4 a3 = *(const float4*)&g_PACC[(size_t)(3*M_TOK + m)*DM + kq*4];
                int h = kq >> 1;
                float s = g_PSUM[0*NH*M_TOK + h*M_TOK + m]
                        + g_PSUM[1*NH*M_TOK + h*M_TOK + m]
                        + g_PSUM[2*NH*M_TOK + h*M_TOK + m]
                        + g_PSUM[3*NH*M_TOK + h*M_TOK + m];
                float inv = 1.f / s;
                v.x = (a0.x+a1.x+a2.x+a3.x)*inv;
                v.y = (a0.y+a1.y+a2.y+a3.y)*inv;
                v.z = (a0.z+a1.z+a2.z+a3.z)*inv;
                v.w = (a0.w+a1.w+a2.w+a3.w)*inv;
            }
            *(float4*)&S.A[r][kq*4] = v;
        }
        #pragma unroll
        for (int idx = tid; idx < 4096; idx += 256){
            int c = idx >> 6, k = idx & 63;
            S.W[c][k] = W[(size_t)(cb + c)*KDIM + ch*64 + k];
        }
        __syncthreads();
        #pragma unroll
        for (int k = 0; k < 64; k += 4){
            ulonglong2 a0 = *(const ulonglong2*)&S.A[rbase+0][k];
            ulonglong2 a1 = *(const ulonglong2*)&S.A[rbase+1][k];
            u64 w0a = *(const u64*)&S.W[c0   ][k];
            u64 w0b = *(const u64*)&S.W[c0   ][k+2];
            u64 w1a = *(const u64*)&S.W[c0+32][k];
            u64 w1b = *(const u64*)&S.W[c0+32][k+2];
            F2_FMA(acc2[0][0], a0.x, w0a); F2_FMA(acc2[0][0], a0.y, w0b);
            F2_FMA(acc2[0][1], a0.x, w1a); F2_FMA(acc2[0][1], a0.y, w1b);
            F2_FMA(acc2[1][0], a1.x, w0a); F2_FMA(acc2[1][0], a1.y, w0b);
            F2_FMA(acc2[1][1], a1.x, w1a); F2_FMA(acc2[1][1], a1.y, w1b);
        }
        __syncthreads();
    }

    const float qs = (EPI == 0 && slice == 0) ? 0.35355339059327373f : 1.0f;
    #pragma unroll
    for (int i = 0; i < 2; i++){
        int m = rb + rbase + i;
        #pragma unroll
        for (int u = 0; u < 2; u++){
            int c = c0 + 32*u;
            unsigned lo, hi;
            UNPACK2(lo, hi, acc2[i][u]);
            float v = __uint_as_float(lo) + __uint_as_float(hi) + bias[cb + c];
            if (EPI == 0){
                v *= qs;
                OUT[((slice*NH + (c >> 3))*M_TOK + m)*HD + (c & 7)] = v;
            } else if (EPI == 1){
                OUT[(size_t)m*ldo + cb + c] = fmaxf(v, 0.f);
            } else {
                S.A[rbase+i][c] = v + RES[m*DM + c];
            }
        }
    }
    if (EPI >= 2){
        __syncthreads();
        int row = tid >> 4, seg = tid & 15;
        float s = 0.f, s2 = 0.f;
        #pragma unroll
        for (int t = 0; t < 4; t++){
            float x = S.A[row][seg*4 + t];
            s += x; s2 = fmaf(x, x, s2);
        }
        #pragma unroll
        for (int off = 8; off > 0; off >>= 1){
            s  += __shfl_xor_sync(0xffffffffu, s,  off);
            s2 += __shfl_xor_sync(0xffffffffu, s2, off);
        }
        float mean = s * (1.f/64.f);
        float var  = fmaf(-mean, mean, s2 * (1.f/64.f));
        float rstd = rsqrtf(var + 1e-5f);
        int m = rb + row;
        if (EPI == 2){
            #pragma unroll
            for (int t = 0; t < 4; t++){
                int c = seg*4 + t;
                OUT[m*DM + c] = (S.A[row][c] - mean) * rstd * lnw[c] + lnb[c];
            }
        } else {   // EPI 4: prune, emit output, row norms
            float nx = 0.f, ny = 0.f;
            #pragma unroll
            for (int t = 0; t < 4; t++){
                int c = seg*4 + t;
                float o  = (S.A[row][c] - mean) * rstd * lnw[c] + lnb[c];
                float xv = o * mask[c];
                OUT[m*DM + c] = xv;
                float yv = RGB[m*DM + c];
                nx = fmaf(xv, xv, nx);
                ny = fmaf(yv, yv, ny);
            }
            #pragma unroll
            for (int off = 8; off > 0; off >>= 1){
                nx += __shfl_xor_sync(0xffffffffu, nx, off);
                ny += __shfl_xor_sync(0xffffffffu, ny, off);
            }
            if (seg == 0){ g_NX[m] = nx; g_NY[m] = ny; }
        }
    }
}

// ---------------- attention unit: 512 queries x 1 head x 1024 keys ---------------
__device__ __forceinline__ void attn_unit(AttnS& S, const float* __restrict__ QKV, int u)
{
    const int tid = threadIdx.x;
    const int mb = u & 7, h = (u >> 3) & 7, ks = u >> 6;
    const int m0 = mb*512 + tid, m1 = m0 + 256;
    const float4* Qb = (const float4*)QKV;
    const float4* K4 = (const float4*)QKV + (size_t)(NH*M_TOK + h*M_TOK)*2;
    const float4* V4 = (const float4*)QKV + (size_t)(2*NH*M_TOK + h*M_TOK)*2;

    const ExpC C = make_expc();
    float4 qa0 = Qb[(size_t)(h*M_TOK + m0)*2], qa1 = Qb[(size_t)(h*M_TOK + m0)*2 + 1];
    float4 qb0 = Qb[(size_t)(h*M_TOK + m1)*2], qb1 = Qb[(size_t)(h*M_TOK + m1)*2 + 1];
    u64 qA[8], qB[8];
    qA[0]=pairbits(__float_as_uint(qa0.x)); qA[1]=pairbits(__float_as_uint(qa0.y));
    qA[2]=pairbits(__float_as_uint(qa0.z)); qA[3]=pairbits(__float_as_uint(qa0.w));
    qA[4]=pairbits(__float_as_uint(qa1.x)); qA[5]=pairbits(__float_as_uint(qa1.y));
    qA[6]=pairbits(__float_as_uint(qa1.z)); qA[7]=pairbits(__float_as_uint(qa1.w));
    qB[0]=pairbits(__float_as_uint(qb0.x)); qB[1]=pairbits(__float_as_uint(qb0.y));
    qB[2]=pairbits(__float_as_uint(qb0.z)); qB[3]=pairbits(__float_as_uint(qb0.w));
    qB[4]=pairbits(__float_as_uint(qb1.x)); qB[5]=pairbits(__float_as_uint(qb1.y));
    qB[6]=pairbits(__float_as_uint(qb1.z)); qB[7]=pairbits(__float_as_uint(qb1.w));

    u64 accA[4] = {0,0,0,0}, accB[4] = {0,0,0,0};
    u64 ssA = 0, ssB = 0;

    __syncthreads();
    for (int kt = 0; kt < 2; kt++){
        int key0 = ks*1024 + kt*512;
        for (int idx = tid; idx < 1024; idx += 256){
            int j = idx >> 1, hf = idx & 1;
            float4 kv = K4[key0*2 + idx];
            float* dst = S.Kp + (j>>1)*16 + hf*8 + (j&1);
            dst[0]=kv.x; dst[2]=kv.y; dst[4]=kv.z; dst[6]=kv.w;
            S.Vs[idx] = V4[key0*2 + idx];
        }
        __syncthreads();
        const ulonglong2* vr = (const ulonglong2*)S.Vs;
        #pragma unroll 4
        for (int jp = 0; jp < 256; jp++){
            const ulonglong2* kr = (const ulonglong2*)(S.Kp + jp*16);
            // all smem loads issued up front so latency overlaps the chains
            ulonglong2 k01 = kr[0], k23 = kr[1], k45 = kr[2], k67 = kr[3];
            ulonglong2 e0 = vr[4*jp],   e1 = vr[4*jp+1];   // even key d0-3, d4-7
            ulonglong2 o0 = vr[4*jp+2], o1 = vr[4*jp+3];   // odd key
            // QK dots: two 4-deep chains per query (halved critical path)
            u64 sA1, sA2, sB1, sB2;
            F2_MUL(sA1, qA[0], k01.x); F2_MUL(sA2, qA[4], k45.x);
            F2_MUL(sB1, qB[0], k01.x); F2_MUL(sB2, qB[4], k45.x);
            F2_FMA(sA1, qA[1], k01.y); F2_FMA(sA2, qA[5], k45.y);
            F2_FMA(sB1, qB[1], k01.y); F2_FMA(sB2, qB[5], k45.y);
            F2_FMA(sA1, qA[2], k23.x); F2_FMA(sA2, qA[6], k67.x);
            F2_FMA(sB1, qB[2], k23.x); F2_FMA(sB2, qB[6], k67.x);
            F2_FMA(sA1, qA[3], k23.y); F2_FMA(sA2, qA[7], k67.y);
            F2_FMA(sB1, qB[3], k23.y); F2_FMA(sB2, qB[7], k67.y);
            F2_ADD(sA1, sA1, sA2);
            F2_ADD(sB1, sB1, sB2);
            unsigned a0r, a1r, b0r, b1r;
            u64 pA = pexp2(sA1, C, a0r, a1r);
            u64 pB = pexp2(sB1, C, b0r, b1r);
            F2_ADD(ssA, ssA, pA);
            F2_ADD(ssB, ssB, pB);
            u64 pA0 = pairbits(a0r), pA1 = pairbits(a1r);
            u64 pB0 = pairbits(b0r), pB1 = pairbits(b1r);
            F2_FMA(accA[0], pA0, e0.x); F2_FMA(accA[1], pA0, e0.y);
            F2_FMA(accA[2], pA0, e1.x); F2_FMA(accA[3], pA0, e1.y);
            F2_FMA(accA[0], pA1, o0.x); F2_FMA(accA[1], pA1, o0.y);
            F2_FMA(accA[2], pA1, o1.x); F2_FMA(accA[3], pA1, o1.y);
            F2_FMA(accB[0], pB0, e0.x); F2_FMA(accB[1], pB0, e0.y);
            F2_FMA(accB[2], pB0, e1.x); F2_FMA(accB[3], pB0, e1.y);
            F2_FMA(accB[0], pB1, o0.x); F2_FMA(accB[1], pB1, o0.y);
            F2_FMA(accB[2], pB1, o1.x); F2_FMA(accB[3], pB1, o1.y);
        }
        __syncthreads();
    }
    u64* PA = (u64*)(g_PACC + (size_t)ks*M_TOK*DM + (size_t)m0*DM + h*HD);
    PA[0]=accA[0]; PA[1]=accA[1]; PA[2]=accA[2]; PA[3]=accA[3];
    u64* PB = (u64*)(g_PACC + (size_t)ks*M_TOK*DM + (size_t)m1*DM + h*HD);
    PB[0]=accB[0]; PB[1]=accB[1]; PB[2]=accB[2]; PB[3]=accB[3];
    unsigned slo, shi;
    UNPACK2(slo, shi, ssA);
    g_PSUM[ks*NH*M_TOK + h*M_TOK + m0] = __uint_as_float(slo) + __uint_as_float(shi);
    UNPACK2(slo, shi, ssB);
    g_PSUM[ks*NH*M_TOK + h*M_TOK + m1] = __uint_as_float(slo) + __uint_as_float(shi);
}

// ---------------- Gaussian-kernel gram sums (f32x2; symmetric tile skip) ---------
template<int KD, int SYM>
__device__ __forceinline__ u64 mmd_tile(const float (*Asm)[68], const float (*Bsm)[68],
                                        const float* na, const float* nb,
                                        int rbase, int ja, int ibase, int jbase,
                                        const ExpC& C)
{
    u64 acc2[4][4] = {};
    #pragma unroll
    for (int k = 0; k < KD; k += 4){
        ulonglong2 a0 = *(const ulonglong2*)&Asm[rbase+0][k];
        ulonglong2 a1 = *(const ulonglong2*)&Asm[rbase+1][k];
        ulonglong2 a2 = *(const ulonglong2*)&Asm[rbase+2][k];
        ulonglong2 a3 = *(const ulonglong2*)&Asm[rbase+3][k];
        ulonglong2 b0 = *(const ulonglong2*)&Bsm[ja    ][k];
        ulonglong2 b1 = *(const ulonglong2*)&Bsm[ja+32 ][k];
        ulonglong2 b2 = *(const ulonglong2*)&Bsm[ja+64 ][k];
        ulonglong2 b3 = *(const ulonglong2*)&Bsm[ja+96 ][k];
        F2_FMA(acc2[0][0], a0.x, b0.x); F2_FMA(acc2[0][0], a0.y, b0.y);
        F2_FMA(acc2[0][1], a0.x, b1.x); F2_FMA(acc2[0][1], a0.y, b1.y);
        F2_FMA(acc2[0][2], a0.x, b2.x); F2_FMA(acc2[0][2], a0.y, b2.y);
        F2_FMA(acc2[0][3], a0.x, b3.x); F2_FMA(acc2[0][3], a0.y, b3.y);
        F2_FMA(acc2[1][0], a1.x, b0.x); F2_FMA(acc2[1][0], a1.y, b0.y);
        F2_FMA(acc2[1][1], a1.x, b1.x); F2_FMA(acc2[1][1], a1.y, b1.y);
        F2_FMA(acc2[1][2], a1.x, b2.x); F2_FMA(acc2[1][2], a1.y, b2.y);
        F2_FMA(acc2[1][3], a1.x, b3.x); F2_FMA(acc2[1][3], a1.y, b3.y);
        F2_FMA(acc2[2][0], a2.x, b0.x); F2_FMA(acc2[2][0], a2.y, b0.y);
        F2_FMA(acc2[2][1], a2.x, b1.x); F2_FMA(acc2[2][1], a2.y, b1.y);
        F2_FMA(acc2[2][2], a2.x, b2.x); F2_FMA(acc2[2][2], a2.y, b2.y);
        F2_FMA(acc2[2][3], a2.x, b3.x); F2_FMA(acc2[2][3], a2.y, b3.y);
        F2_FMA(acc2[3][0], a3.x, b0.x); F2_FMA(acc2[3][0], a3.y, b0.y);
        F2_FMA(acc2[3][1], a3.x, b1.x); F2_FMA(acc2[3][1], a3.y, b1.y);
        F2_FMA(acc2[3][2], a3.x, b2.x); F2_FMA(acc2[3][2], a3.y, b2.y);
        F2_FMA(acc2[3][3], a3.x, b3.x); F2_FMA(acc2[3][3], a3.y, b3.y);
    }
    u64 psum2 = 0;
    #pragma unroll
    for (int i = 0; i < 4; i++){
        float nai = na[rbase+i];
        float x[4];
        #pragma unroll
        for (int u = 0; u < 4; u++){
            unsigned lo, hi; UNPACK2(lo, hi, acc2[i][u]);
            float dot = __uint_as_float(lo) + __uint_as_float(hi);
            float d = nai + nb[ja + 32*u] - 2.f*dot;
            x[u] = fminf(d, 150.f) * -0.5f;
            if (SYM){
                if (jbase + 32*u <= ibase + i) x[u] = -85.f;
            }
        }
        u64 s01, s23;
        PACK2(s01, __float_as_uint(x[0]), __float_as_uint(x[1]));
        PACK2(s23, __float_as_uint(x[2]), __float_as_uint(x[3]));
        unsigned d0, d1;
        u64 p01 = pexp2(s01, C, d0, d1);
        u64 p23 = pexp2(s23, C, d0, d1);
        F2_ADD(psum2, psum2, p01);
        F2_ADD(psum2, psum2, p23);
    }
    return psum2;
}

__device__ __forceinline__ void mmd_unit(MmdS& S, int u,
                                         const float* __restrict__ XP,
                                         const float* __restrict__ RGB)
{
    const int type = u >> 7, ib4 = u & 127;
    const float *A, *B, *NA, *NB;
    if (type == 0){ A = XP;  B = XP;  NA = g_NX; NB = g_NX; }
    else if (type == 1){ A = RGB; B = RGB; NA = g_NY; NB = g_NY; }
    else { A = XP; B = RGB; NA = g_NX; NB = g_NY; }
    const int kd  = (type == 1) ? 64 : g_kd;
    const int sym = (type != 2);
    const ExpC C = make_expc();

    const int tid = threadIdx.x;
    const int ib  = ib4 * 32;
    for (int idx = tid; idx < 512; idx += 256){
        int r = idx >> 4, kq = idx & 15;
        *(float4*)&S.A[r][kq*4] = ((const float4*)A)[(ib + r)*16 + kq];
    }
    if (tid < 32) S.na[tid] = NA[ib + tid];

    const int ja = tid & 31, rbase = (tid >> 5) * 4;
    const int ibase = ib + rbase;
    u64 psum2 = 0;
    for (int jt = 0; jt < 32; jt++){
        if (sym && jt*128 + 127 <= ib) continue;
        __syncthreads();
        for (int idx = tid; idx < 2048; idx += 256){
            int r = idx >> 4, kq = idx & 15;
            *(float4*)&S.B[r][kq*4] = ((const float4*)B)[(jt*128 + r)*16 + kq];
        }
        if (tid < 128) S.nb[tid] = NB[jt*128 + tid];
        __syncthreads();
        const int jbase = jt*128 + ja;
        u64 t;
        if (sym){
            if (kd == 32) t = mmd_tile<32,1>(S.A, S.B, S.na, S.nb, rbase, ja, ibase, jbase, C);
            else          t = mmd_tile<64,1>(S.A, S.B, S.na, S.nb, rbase, ja, ibase, jbase, C);
        } else {
            if (kd == 32) t = mmd_tile<32,0>(S.A, S.B, S.na, S.nb, rbase, ja, ibase, jbase, C);
            else          t = mmd_tile<64,0>(S.A, S.B, S.na, S.nb, rbase, ja, ibase, jbase, C);
        }
        F2_ADD(psum2, psum2, t);
    }
    unsigned lo, hi; UNPACK2(lo, hi, psum2);
    __syncthreads();
    S.red[tid] = __uint_as_float(lo) + __uint_as_float(hi);
    __syncthreads();
    for (int s = 128; s > 0; s >>= 1){
        if (tid < s) S.red[tid] += S.red[tid + s];
        __syncthreads();
    }
    if (tid == 0) g_PART[type*128 + ib4] = S.red[0];
}

// ---------------- init + megakernel ----------------------------------------------
__global__ void k_init(){
    g_barcnt = 0;
    g_work = 0;
}

__global__ __launch_bounds__(256, 2) void k_mega(
    const float* __restrict__ hsi, const float* __restrict__ rgb,
    const float* __restrict__ in_w, const float* __restrict__ in_b,
    const float* __restrict__ ow,   const float* __restrict__ ob,
    const float* __restrict__ l1w,  const float* __restrict__ l1b,
    const float* __restrict__ l2w,  const float* __restrict__ l2b,
    const float* __restrict__ n1w,  const float* __restrict__ n1b,
    const float* __restrict__ n2w,  const float* __restrict__ n2b,
    const float* __restrict__ mask, float* __restrict__ dout, int out_size)
{
    __shared__ SmemU SM;
    __shared__ int s_u;
    const int cta = blockIdx.x, tid = threadIdx.x;
    const int rb = cta * 16;
    unsigned phase = 0;

    for (int l = 0; l < NLAYER; l++){
        const float* Xin = (l == 0) ? hsi : g_X;
        // QKV: 3 col-slices, q pre-scaled, head-layout scatter
        #pragma unroll
        for (int s = 0; s < 3; s++)
            gemm16<64,0,0>(SM.g, rb, s*64, s, Xin, in_w + l*192*64, in_b + l*192,
                           nullptr, nullptr, nullptr, g_QKV, 0, nullptr, nullptr);
        gridbar(phase);                      // attention reads all tokens' K/V
        // attention: unit = (mb, h, ks), one per CTA
        attn_unit(SM.a, g_QKV, cta);
        gridbar(phase);                      // proj combine reads cross-CTA PACC
        // out-proj (split-K combine as A) + residual + LN1
        gemm16<64,2,1>(SM.g, rb, 0, 0, nullptr, ow + l*64*64, ob + l*64,
                       Xin, n1w + l*64, n1b + l*64, g_X, 64, nullptr, nullptr);
        // FF1 (ReLU): 4 col-slices — row-aligned with proj, no barrier needed
        #pragma unroll
        for (int s = 0; s < 4; s++)
            gemm16<64,1,0>(SM.g, rb, s*64, 0, g_X, l1w + l*256*64, l1b + l*256,
                           nullptr, nullptr, nullptr, g_F1, 256, nullptr, nullptr);
        // FF2 + residual + LN2 (+ final layer: prune, output, norms) — row-aligned
        if (l < NLAYER-1){
            gemm16<256,2,0>(SM.g, rb, 0, 0, g_F1, l2w + l*64*256, l2b + l*64,
                            g_X, n2w + l*64, n2b + l*64, g_X, 64, nullptr, nullptr);
        } else {
            gemm16<256,4,0>(SM.g, rb, 0, 0, g_F1, l2w + l*64*256, l2b + l*64,
                            g_X, n2w + l*64, n2b + l*64, dout, 64, mask, rgb);
            if (cta == 0 && tid < 32){
                unsigned any = __ballot_sync(0xffffffffu, mask[32 + tid] != 0.f);
                if (tid == 0) g_kd = any ? 64 : 32;
            }
        }
    }
    gridbar(phase);                          // MMD reads all dout rows + norms + kd
    // MMD: atomic work queue over 384 units (deterministic: per-unit g_PART slot)
    for (;;){
        __syncthreads();
        if (tid == 0) s_u = atomicAdd(&g_work, 1);
        __syncthreads();
        int u = s_u;
        if (u >= 384) break;
        mmd_unit(SM.m, u, dout, rgb);
    }
    gridbar(phase);                          // final reduce reads all g_PART
    if (cta == 0 && tid < 32){
        float s[3];
        #pragma unroll
        for (int t = 0; t < 3; t++){
            float v = 0.f;
            for (int i = tid; i < 128; i += 32) v += g_PART[t*128 + i];
            #pragma unroll
            for (int off = 16; off > 0; off >>= 1) v += __shfl_xor_sync(0xffffffffu, v, off);
            s[t] = v;
        }
        if (tid == 0 && out_size > M_TOK*DM){
            const float inv = 1.f / 16777216.f;   // 1/(4096*4096)
            float s0 = 2.f*s[0] + 4096.f;         // strict-upper -> full (sym + diag)
            float s1 = 2.f*s[1] + 4096.f;
            dout[M_TOK*DM] = (s0 + s1 - 2.f*s[2]) * inv;
        }
    }
}

// ---------------- host orchestration ---------------------------------------------
extern "C" void kernel_launch(void* const* d_in, const int* in_sizes, int n_in,
                              void* d_out, int out_size)
{
    (void)in_sizes; (void)n_in;
    const float* hsi  = (const float*)d_in[0];
    const float* rgb  = (const float*)d_in[1];
    const float* in_w = (const float*)d_in[2];
    const float* in_b = (const float*)d_in[3];
    const float* ow   = (const float*)d_in[4];
    const float* ob   = (const float*)d_in[5];
    const float* l1w  = (const float*)d_in[6];
    const float* l1b  = (const float*)d_in[7];
    const float* l2w  = (const float*)d_in[8];
    const float* l2b  = (const float*)d_in[9];
    const float* n1w  = (const float*)d_in[10];
    const float* n1b  = (const float*)d_in[11];
    const float* n2w  = (const float*)d_in[12];
    const float* n2b  = (const float*)d_in[13];
    const float* mask = (const float*)d_in[14];
    float* dout = (float*)d_out;

    k_init<<<1, 1>>>();
    k_mega<<<GRID, 256>>>(hsi, rgb, in_w, in_b, ow, ob, l1w, l1b, l2w, l2b,
                          n1w, n1b, n2w, n2b, mask, dout, out_size);
}

// round 16
// speedup vs baseline: 1.2636x; 1.1302x over previous
#include <cuda_runtime.h>

#define M_TOK 4096
#define DM    64
#define NH    8
#define HD    8
#define DFF   256
#define NLAYER 4
#define KSPLIT 4
#define GRID  256

typedef unsigned long long u64;

// ---------------- scratch (device globals; no allocation allowed) ----------------
__device__ unsigned g_barcnt;
__device__ int      g_work;
__device__ __align__(16) float g_X   [M_TOK*DM];
__device__ __align__(16) float g_QKV [3*NH*M_TOK*HD];
__device__ __align__(16) float g_F1  [M_TOK*DFF];
__device__ __align__(16) float g_PACC[KSPLIT*M_TOK*DM];
__device__ __align__(16) float g_PSUM[KSPLIT*NH*M_TOK];
__device__ float g_NX[M_TOK];
__device__ float g_NY[M_TOK];
__device__ float g_PART[3*128];
__device__ int   g_kd;

// ---------------- packed f32x2 helpers (SASS FFMA2: only reachable via PTX) ------
#define F2_FMA3(d,a,b,c) asm("fma.rn.f32x2 %0,%1,%2,%3;" : "=l"(d) : "l"(a),"l"(b),"l"(c))
#define F2_FMA(d,a,b)    asm("fma.rn.f32x2 %0,%1,%2,%0;" : "+l"(d) : "l"(a),"l"(b))
#define F2_MUL(d,a,b)    asm("mul.rn.f32x2 %0,%1,%2;"    : "=l"(d) : "l"(a),"l"(b))
#define F2_ADD(d,a,b)    asm("add.rn.f32x2 %0,%1,%2;"    : "+l"(d) : "l"(a),"l"(b))
#define PACK2(d,lo,hi)   asm("mov.b64 %0,{%1,%2};" : "=l"(d) : "r"(lo),"r"(hi))
#define UNPACK2(lo,hi,s) asm("mov.b64 {%0,%1},%2;" : "=r"(lo),"=r"(hi) : "l"(s))
// exp2 on the MUFU pipe (runs concurrently with the saturated fma pipe)
#define EX2(d,sbits)     asm("ex2.approx.f32 %0, %1;" : "=f"(d) : "f"(__uint_as_float(sbits)))

__device__ __forceinline__ u64 pairbits(unsigned x){
    u64 r; asm("mov.b64 %0,{%1,%1};" : "=l"(r) : "r"(x)); return r;
}

#define LOG2E  1.4426950408889634f
#define NL2EH -0.7213475204444817f    // -log2(e)/2

// ---------------- shared memory union (45.2 KB -> 2 CTAs/SM guaranteed) ----------
struct GemmS { float A[16][68]; float W[64][66]; };
struct AttnS { float Kp[4096]; float4 Vs[1024]; };
struct MmdS  { float A[32][68]; float B[128][68]; float na[32]; float nb[128]; float red[256]; };
union SmemU { GemmS g; AttnS a; MmdS m; };

// ---------------- grid barrier: release-arrive + acquire-load poll (no RMW spin) -
__device__ __forceinline__ void gridbar(unsigned& phase){
    __syncthreads();
    phase += 1;
    if (threadIdx.x == 0){
        __threadfence();                       // release
        atomicAdd(&g_barcnt, 1u);
        const unsigned target = phase*GRID;
        unsigned v;
        do {
            asm volatile("ld.global.acquire.gpu.u32 %0, [%1];"
                         : "=r"(v) : "l"(&g_barcnt));
        } while (v < target);
    }
    __syncthreads();
}

// ---------------- 16-row GEMM tile: C[rb..rb+16, cb..cb+64] = A @ W^T + b --------
// ASRC 0: A from global (lda = KDIM); ASRC 1: A = split-K attention combine.
// EPI 0: scatter to Q/K/V head layout (q scaled by log2e/sqrt(hd)); EPI 1: ReLU;
// EPI 2: +res, LN; EPI 4: +res, LN, *mask -> OUT(dout), row norms NX/NY.
template<int KDIM, int EPI, int ASRC>
__device__ __forceinline__ void gemm16(
    GemmS& S, int rb, int cb, int slice,
    const float* __restrict__ A,
    const float* __restrict__ W,
    const float* __restrict__ bias,
    const float* __restrict__ RES,
    const float* __restrict__ lnw, const float* __restrict__ lnb,
    float* __restrict__ OUT, int ldo,
    const float* __restrict__ mask, const float* __restrict__ RGB)
{
    const int tid = threadIdx.x;
    const int c0  = tid & 31;
    const int rbase = (tid >> 5) * 2;
    u64 acc2[2][2] = {};

    __syncthreads();   // protect smem reuse from previous stage's reads
    #pragma unroll
    for (int ch = 0; ch < KDIM/64; ch++){
        {
            int r = tid >> 4, kq = tid & 15;     // 256 float4s, one per thread
            float4 v;
            if (ASRC == 0){
                v = ((const float4*)(A + (size_t)(rb + r)*KDIM + ch*64))[kq];
            } else {
                int m = rb + r;
                float4 a0 = *(const float4*)&g_PACC[(size_t)(0*M_TOK + m)*DM + kq*4];
                float4 a1 = *(const float4*)&g_PACC[(size_t)(1*M_TOK + m)*DM + kq*4];
                float4 a2 = *(const float4*)&g_PACC[(size_t)(2*M_TOK + m)*DM + kq*4];
                float4 a3 = *(const float4*)&g_PACC[(size_t)(3*M_TOK + m)*DM + kq*4];
                int h = kq >> 1;
                float s = g_PSUM[0*NH*M_TOK + h*M_TOK + m]
                        + g_PSUM[1*NH*M_TOK + h*M_TOK + m]
                        + g_PSUM[2*NH*M_TOK + h*M_TOK + m]
                        + g_PSUM[3*NH*M_TOK + h*M_TOK + m];
                float inv = 1.f / s;
                v.x = (a0.x+a1.x+a2.x+a3.x)*inv;
                v.y = (a0.y+a1.y+a2.y+a3.y)*inv;
                v.z = (a0.z+a1.z+a2.z+a3.z)*inv;
                v.w = (a0.w+a1.w+a2.w+a3.w)*inv;
            }
            *(float4*)&S.A[r][kq*4] = v;
        }
        #pragma unroll
        for (int idx = tid; idx < 4096; idx += 256){
            int c = idx >> 6, k = idx & 63;
            S.W[c][k] = W[(size_t)(cb + c)*KDIM + ch*64 + k];
        }
        __syncthreads();
        #pragma unroll
        for (int k = 0; k < 64; k += 4){
            ulonglong2 a0 = *(const ulonglong2*)&S.A[rbase+0][k];
            ulonglong2 a1 = *(const ulonglong2*)&S.A[rbase+1][k];
            u64 w0a = *(const u64*)&S.W[c0   ][k];
            u64 w0b = *(const u64*)&S.W[c0   ][k+2];
            u64 w1a = *(const u64*)&S.W[c0+32][k];
            u64 w1b = *(const u64*)&S.W[c0+32][k+2];
            F2_FMA(acc2[0][0], a0.x, w0a); F2_FMA(acc2[0][0], a0.y, w0b);
            F2_FMA(acc2[0][1], a0.x, w1a); F2_FMA(acc2[0][1], a0.y, w1b);
            F2_FMA(acc2[1][0], a1.x, w0a); F2_FMA(acc2[1][0], a1.y, w0b);
            F2_FMA(acc2[1][1], a1.x, w1a); F2_FMA(acc2[1][1], a1.y, w1b);
        }
        __syncthreads();
    }

    // Q scale folds 1/sqrt(hd) AND log2(e): logits come out in exp2 domain.
    const float qs = (EPI == 0 && slice == 0) ? 0.51012678299116750f : 1.0f;
    #pragma unroll
    for (int i = 0; i < 2; i++){
        int m = rb + rbase + i;
        #pragma unroll
        for (int u = 0; u < 2; u++){
            int c = c0 + 32*u;
            unsigned lo, hi;
            UNPACK2(lo, hi, acc2[i][u]);
            float v = __uint_as_float(lo) + __uint_as_float(hi) + bias[cb + c];
            if (EPI == 0){
                v *= qs;
                OUT[((slice*NH + (c >> 3))*M_TOK + m)*HD + (c & 7)] = v;
            } else if (EPI == 1){
                OUT[(size_t)m*ldo + cb + c] = fmaxf(v, 0.f);
            } else {
                S.A[rbase+i][c] = v + RES[m*DM + c];
            }
        }
    }
    if (EPI >= 2){
        __syncthreads();
        int row = tid >> 4, seg = tid & 15;
        float s = 0.f, s2 = 0.f;
        #pragma unroll
        for (int t = 0; t < 4; t++){
            float x = S.A[row][seg*4 + t];
            s += x; s2 = fmaf(x, x, s2);
        }
        #pragma unroll
        for (int off = 8; off > 0; off >>= 1){
            s  += __shfl_xor_sync(0xffffffffu, s,  off);
            s2 += __shfl_xor_sync(0xffffffffu, s2, off);
        }
        float mean = s * (1.f/64.f);
        float var  = fmaf(-mean, mean, s2 * (1.f/64.f));
        float rstd = rsqrtf(var + 1e-5f);
        int m = rb + row;
        if (EPI == 2){
            #pragma unroll
            for (int t = 0; t < 4; t++){
                int c = seg*4 + t;
                OUT[m*DM + c] = (S.A[row][c] - mean) * rstd * lnw[c] + lnb[c];
            }
        } else {   // EPI 4: prune, emit output, row norms
            float nx = 0.f, ny = 0.f;
            #pragma unroll
            for (int t = 0; t < 4; t++){
                int c = seg*4 + t;
                float o  = (S.A[row][c] - mean) * rstd * lnw[c] + lnb[c];
                float xv = o * mask[c];
                OUT[m*DM + c] = xv;
                float yv = RGB[m*DM + c];
                nx = fmaf(xv, xv, nx);
                ny = fmaf(yv, yv, ny);
            }
            #pragma unroll
            for (int off = 8; off > 0; off >>= 1){
                nx += __shfl_xor_sync(0xffffffffu, nx, off);
                ny += __shfl_xor_sync(0xffffffffu, ny, off);
            }
            if (seg == 0){ g_NX[m] = nx; g_NY[m] = ny; }
        }
    }
}

// ---------------- attention unit: 512 queries x 1 head x 1024 keys ---------------
// Q pre-scaled by log2e/sqrt(hd): p = exp2(QK) via MUFU.EX2 — no fma-pipe exp.
__device__ __forceinline__ void attn_unit(AttnS& S, const float* __restrict__ QKV, int u)
{
    const int tid = threadIdx.x;
    const int mb = u & 7, h = (u >> 3) & 7, ks = u >> 6;
    const int m0 = mb*512 + tid, m1 = m0 + 256;
    const float4* Qb = (const float4*)QKV;
    const float4* K4 = (const float4*)QKV + (size_t)(NH*M_TOK + h*M_TOK)*2;
    const float4* V4 = (const float4*)QKV + (size_t)(2*NH*M_TOK + h*M_TOK)*2;

    float4 qa0 = Qb[(size_t)(h*M_TOK + m0)*2], qa1 = Qb[(size_t)(h*M_TOK + m0)*2 + 1];
    float4 qb0 = Qb[(size_t)(h*M_TOK + m1)*2], qb1 = Qb[(size_t)(h*M_TOK + m1)*2 + 1];
    u64 qA[8], qB[8];
    qA[0]=pairbits(__float_as_uint(qa0.x)); qA[1]=pairbits(__float_as_uint(qa0.y));
    qA[2]=pairbits(__float_as_uint(qa0.z)); qA[3]=pairbits(__float_as_uint(qa0.w));
    qA[4]=pairbits(__float_as_uint(qa1.x)); qA[5]=pairbits(__float_as_uint(qa1.y));
    qA[6]=pairbits(__float_as_uint(qa1.z)); qA[7]=pairbits(__float_as_uint(qa1.w));
    qB[0]=pairbits(__float_as_uint(qb0.x)); qB[1]=pairbits(__float_as_uint(qb0.y));
    qB[2]=pairbits(__float_as_uint(qb0.z)); qB[3]=pairbits(__float_as_uint(qb0.w));
    qB[4]=pairbits(__float_as_uint(qb1.x)); qB[5]=pairbits(__float_as_uint(qb1.y));
    qB[6]=pairbits(__float_as_uint(qb1.z)); qB[7]=pairbits(__float_as_uint(qb1.w));

    u64 accA[4] = {0,0,0,0}, accB[4] = {0,0,0,0};
    u64 ssA = 0, ssB = 0;

    __syncthreads();
    for (int kt = 0; kt < 2; kt++){
        int key0 = ks*1024 + kt*512;
        for (int idx = tid; idx < 1024; idx += 256){
            int j = idx >> 1, hf = idx & 1;
            float4 kv = K4[key0*2 + idx];
            float* dst = S.Kp + (j>>1)*16 + hf*8 + (j&1);
            dst[0]=kv.x; dst[2]=kv.y; dst[4]=kv.z; dst[6]=kv.w;
            S.Vs[idx] = V4[key0*2 + idx];
        }
        __syncthreads();
        const ulonglong2* vr = (const ulonglong2*)S.Vs;
        #pragma unroll 4
        for (int jp = 0; jp < 256; jp++){
            const ulonglong2* kr = (const ulonglong2*)(S.Kp + jp*16);
            // all smem loads issued up front so latency overlaps the chains
            ulonglong2 k01 = kr[0], k23 = kr[1], k45 = kr[2], k67 = kr[3];
            ulonglong2 e0 = vr[4*jp],   e1 = vr[4*jp+1];   // even key d0-3, d4-7
            ulonglong2 o0 = vr[4*jp+2], o1 = vr[4*jp+3];   // odd key
            // QK dots in exp2 domain: two 4-deep chains per query
            u64 sA1, sA2, sB1, sB2;
            F2_MUL(sA1, qA[0], k01.x); F2_MUL(sA2, qA[4], k45.x);
            F2_MUL(sB1, qB[0], k01.x); F2_MUL(sB2, qB[4], k45.x);
            F2_FMA(sA1, qA[1], k01.y); F2_FMA(sA2, qA[5], k45.y);
            F2_FMA(sB1, qB[1], k01.y); F2_FMA(sB2, qB[5], k45.y);
            F2_FMA(sA1, qA[2], k23.x); F2_FMA(sA2, qA[6], k67.x);
            F2_FMA(sB1, qB[2], k23.x); F2_FMA(sB2, qB[6], k67.x);
            F2_FMA(sA1, qA[3], k23.y); F2_FMA(sA2, qA[7], k67.y);
            F2_FMA(sB1, qB[3], k23.y); F2_FMA(sB2, qB[7], k67.y);
            F2_ADD(sA1, sA1, sA2);
            F2_ADD(sB1, sB1, sB2);
            // exp2 on the MUFU pipe (concurrent with fma pipe)
            unsigned al, ah, bl, bh;
            UNPACK2(al, ah, sA1); UNPACK2(bl, bh, sB1);
            float ea0, ea1, eb0, eb1;
            EX2(ea0, al); EX2(ea1, ah); EX2(eb0, bl); EX2(eb1, bh);
            u64 pA0 = pairbits(__float_as_uint(ea0)), pA1 = pairbits(__float_as_uint(ea1));
            u64 pB0 = pairbits(__float_as_uint(eb0)), pB1 = pairbits(__float_as_uint(eb1));
            u64 pA, pB;
            PACK2(pA, __float_as_uint(ea0), __float_as_uint(ea1));
            PACK2(pB, __float_as_uint(eb0), __float_as_uint(eb1));
            F2_ADD(ssA, ssA, pA);
            F2_ADD(ssB, ssB, pB);
            F2_FMA(accA[0], pA0, e0.x); F2_FMA(accA[1], pA0, e0.y);
            F2_FMA(accA[2], pA0, e1.x); F2_FMA(accA[3], pA0, e1.y);
            F2_FMA(accA[0], pA1, o0.x); F2_FMA(accA[1], pA1, o0.y);
            F2_FMA(accA[2], pA1, o1.x); F2_FMA(accA[3], pA1, o1.y);
            F2_FMA(accB[0], pB0, e0.x); F2_FMA(accB[1], pB0, e0.y);
            F2_FMA(accB[2], pB0, e1.x); F2_FMA(accB[3], pB0, e1.y);
            F2_FMA(accB[0], pB1, o0.x); F2_FMA(accB[1], pB1, o0.y);
            F2_FMA(accB[2], pB1, o1.x); F2_FMA(accB[3], pB1, o1.y);
        }
        __syncthreads();
    }
    u64* PA = (u64*)(g_PACC + (size_t)ks*M_TOK*DM + (size_t)m0*DM + h*HD);
    PA[0]=accA[0]; PA[1]=accA[1]; PA[2]=accA[2]; PA[3]=accA[3];
    u64* PB = (u64*)(g_PACC + (size_t)ks*M_TOK*DM + (size_t)m1*DM + h*HD);
    PB[0]=accB[0]; PB[1]=accB[1]; PB[2]=accB[2]; PB[3]=accB[3];
    unsigned slo, shi;
    UNPACK2(slo, shi, ssA);
    g_PSUM[ks*NH*M_TOK + h*M_TOK + m0] = __uint_as_float(slo) + __uint_as_float(shi);
    UNPACK2(slo, shi, ssB);
    g_PSUM[ks*NH*M_TOK + h*M_TOK + m1] = __uint_as_float(slo) + __uint_as_float(shi);
}

// ---------------- Gaussian-kernel gram sums (f32x2 dots; EX2 on MUFU) ------------
// na/nb are pre-scaled by -log2(e)/2, so x = na' + nb' + log2e*dot and p = exp2(x).
template<int KD, int SYM>
__device__ __forceinline__ u64 mmd_tile(const float (*Asm)[68], const float (*Bsm)[68],
                                        const float* na, const float* nb,
                                        int rbase, int ja, int ibase, int jbase)
{
    u64 acc2[4][4] = {};
    #pragma unroll
    for (int k = 0; k < KD; k += 4){
        ulonglong2 a0 = *(const ulonglong2*)&Asm[rbase+0][k];
        ulonglong2 a1 = *(const ulonglong2*)&Asm[rbase+1][k];
        ulonglong2 a2 = *(const ulonglong2*)&Asm[rbase+2][k];
        ulonglong2 a3 = *(const ulonglong2*)&Asm[rbase+3][k];
        ulonglong2 b0 = *(const ulonglong2*)&Bsm[ja    ][k];
        ulonglong2 b1 = *(const ulonglong2*)&Bsm[ja+32 ][k];
        ulonglong2 b2 = *(const ulonglong2*)&Bsm[ja+64 ][k];
        ulonglong2 b3 = *(const ulonglong2*)&Bsm[ja+96 ][k];
        F2_FMA(acc2[0][0], a0.x, b0.x); F2_FMA(acc2[0][0], a0.y, b0.y);
        F2_FMA(acc2[0][1], a0.x, b1.x); F2_FMA(acc2[0][1], a0.y, b1.y);
        F2_FMA(acc2[0][2], a0.x, b2.x); F2_FMA(acc2[0][2], a0.y, b2.y);
        F2_FMA(acc2[0][3], a0.x, b3.x); F2_FMA(acc2[0][3], a0.y, b3.y);
        F2_FMA(acc2[1][0], a1.x, b0.x); F2_FMA(acc2[1][0], a1.y, b0.y);
        F2_FMA(acc2[1][1], a1.x, b1.x); F2_FMA(acc2[1][1], a1.y, b1.y);
        F2_FMA(acc2[1][2], a1.x, b2.x); F2_FMA(acc2[1][2], a1.y, b2.y);
        F2_FMA(acc2[1][3], a1.x, b3.x); F2_FMA(acc2[1][3], a1.y, b3.y);
        F2_FMA(acc2[2][0], a2.x, b0.x); F2_FMA(acc2[2][0], a2.y, b0.y);
        F2_FMA(acc2[2][1], a2.x, b1.x); F2_FMA(acc2[2][1], a2.y, b1.y);
        F2_FMA(acc2[2][2], a2.x, b2.x); F2_FMA(acc2[2][2], a2.y, b2.y);
        F2_FMA(acc2[2][3], a2.x, b3.x); F2_FMA(acc2[2][3], a2.y, b3.y);
        F2_FMA(acc2[3][0], a3.x, b0.x); F2_FMA(acc2[3][0], a3.y, b0.y);
        F2_FMA(acc2[3][1], a3.x, b1.x); F2_FMA(acc2[3][1], a3.y, b1.y);
        F2_FMA(acc2[3][2], a3.x, b2.x); F2_FMA(acc2[3][2], a3.y, b2.y);
        F2_FMA(acc2[3][3], a3.x, b3.x); F2_FMA(acc2[3][3], a3.y, b3.y);
    }
    u64 psum2 = 0;
    #pragma unroll
    for (int i = 0; i < 4; i++){
        float nai = na[rbase+i];
        float p[4];
        #pragma unroll
        for (int u = 0; u < 4; u++){
            unsigned lo, hi; UNPACK2(lo, hi, acc2[i][u]);
            float dot = __uint_as_float(lo) + __uint_as_float(hi);
            float x = fmaf(dot, LOG2E, nai + nb[ja + 32*u]);
            if (SYM){
                if (jbase + 32*u <= ibase + i) x = -200.f;   // exp2 -> 0
            }
            EX2(p[u], __float_as_uint(x));
        }
        u64 s01, s23;
        PACK2(s01, __float_as_uint(p[0]), __float_as_uint(p[1]));
        PACK2(s23, __float_as_uint(p[2]), __float_as_uint(p[3]));
        F2_ADD(psum2, psum2, s01);
        F2_ADD(psum2, psum2, s23);
    }
    return psum2;
}

__device__ __forceinline__ void mmd_unit(MmdS& S, int u,
                                         const float* __restrict__ XP,
                                         const float* __restrict__ RGB)
{
    const int type = u >> 7, ib4 = u & 127;
    const float *A, *B, *NA, *NB;
    if (type == 0){ A = XP;  B = XP;  NA = g_NX; NB = g_NX; }
    else if (type == 1){ A = RGB; B = RGB; NA = g_NY; NB = g_NY; }
    else { A = XP; B = RGB; NA = g_NX; NB = g_NY; }
    const int kd  = (type == 1) ? 64 : g_kd;
    const int sym = (type != 2);

    const int tid = threadIdx.x;
    const int ib  = ib4 * 32;
    for (int idx = tid; idx < 512; idx += 256){
        int r = idx >> 4, kq = idx & 15;
        *(float4*)&S.A[r][kq*4] = ((const float4*)A)[(ib + r)*16 + kq];
    }
    if (tid < 32) S.na[tid] = NA[ib + tid] * NL2EH;    // pre-scale: -log2e/2 * ||a||^2

    const int ja = tid & 31, rbase = (tid >> 5) * 4;
    const int ibase = ib + rbase;
    u64 psum2 = 0;
    for (int jt = 0; jt < 32; jt++){
        if (sym && jt*128 + 127 <= ib) continue;
        __syncthreads();
        for (int idx = tid; idx < 2048; idx += 256){
            int r = idx >> 4, kq = idx & 15;
            *(float4*)&S.B[r][kq*4] = ((const float4*)B)[(jt*128 + r)*16 + kq];
        }
        if (tid < 128) S.nb[tid] = NB[jt*128 + tid] * NL2EH;
        __syncthreads();
        const int jbase = jt*128 + ja;
        u64 t;
        if (sym){
            if (kd == 32) t = mmd_tile<32,1>(S.A, S.B, S.na, S.nb, rbase, ja, ibase, jbase);
            else          t = mmd_tile<64,1>(S.A, S.B, S.na, S.nb, rbase, ja, ibase, jbase);
        } else {
            if (kd == 32) t = mmd_tile<32,0>(S.A, S.B, S.na, S.nb, rbase, ja, ibase, jbase);
            else          t = mmd_tile<64,0>(S.A, S.B, S.na, S.nb, rbase, ja, ibase, jbase);
        }
        F2_ADD(psum2, psum2, t);
    }
    unsigned lo, hi; UNPACK2(lo, hi, psum2);
    __syncthreads();
    S.red[tid] = __uint_as_float(lo) + __uint_as_float(hi);
    __syncthreads();
    for (int s = 128; s > 0; s >>= 1){
        if (tid < s) S.red[tid] += S.red[tid + s];
        __syncthreads();
    }
    if (tid == 0) g_PART[type*128 + ib4] = S.red[0];
}

// ---------------- init + megakernel ----------------------------------------------
__global__ void k_init(){
    g_barcnt = 0;
    g_work = 0;
}

__global__ __launch_bounds__(256, 2) void k_mega(
    const float* __restrict__ hsi, const float* __restrict__ rgb,
    const float* __restrict__ in_w, const float* __restrict__ in_b,
    const float* __restrict__ ow,   const float* __restrict__ ob,
    const float* __restrict__ l1w,  const float* __restrict__ l1b,
    const float* __restrict__ l2w,  const float* __restrict__ l2b,
    const float* __restrict__ n1w,  const float* __restrict__ n1b,
    const float* __restrict__ n2w,  const float* __restrict__ n2b,
    const float* __restrict__ mask, float* __restrict__ dout, int out_size)
{
    __shared__ SmemU SM;
    __shared__ int s_u;
    const int cta = blockIdx.x, tid = threadIdx.x;
    const int rb = cta * 16;
    unsigned phase = 0;

    for (int l = 0; l < NLAYER; l++){
        const float* Xin = (l == 0) ? hsi : g_X;
        // QKV: 3 col-slices, q pre-scaled (1/sqrt(hd) * log2e), head-layout scatter
        #pragma unroll
        for (int s = 0; s < 3; s++)
            gemm16<64,0,0>(SM.g, rb, s*64, s, Xin, in_w + l*192*64, in_b + l*192,
                           nullptr, nullptr, nullptr, g_QKV, 0, nullptr, nullptr);
        gridbar(phase);                      // attention reads all tokens' K/V
        // attention: unit = (mb, h, ks), one per CTA
        attn_unit(SM.a, g_QKV, cta);
        gridbar(phase);                      // proj combine reads cross-CTA PACC
        // out-proj (split-K combine as A) + residual + LN1
        gemm16<64,2,1>(SM.g, rb, 0, 0, nullptr, ow + l*64*64, ob + l*64,
                       Xin, n1w + l*64, n1b + l*64, g_X, 64, nullptr, nullptr);
        // FF1 (ReLU): 4 col-slices — row-aligned with proj, no barrier needed
        #pragma unroll
        for (int s = 0; s < 4; s++)
            gemm16<64,1,0>(SM.g, rb, s*64, 0, g_X, l1w + l*256*64, l1b + l*256,
                           nullptr, nullptr, nullptr, g_F1, 256, nullptr, nullptr);
        // FF2 + residual + LN2 (+ final layer: prune, output, norms) — row-aligned
        if (l < NLAYER-1){
            gemm16<256,2,0>(SM.g, rb, 0, 0, g_F1, l2w + l*64*256, l2b + l*64,
                            g_X, n2w + l*64, n2b + l*64, g_X, 64, nullptr, nullptr);
        } else {
            gemm16<256,4,0>(SM.g, rb, 0, 0, g_F1, l2w + l*64*256, l2b + l*64,
                            g_X, n2w + l*64, n2b + l*64, dout, 64, mask, rgb);
            if (cta == 0 && tid < 32){
                unsigned any = __ballot_sync(0xffffffffu, mask[32 + tid] != 0.f);
                if (tid == 0) g_kd = any ? 64 : 32;
            }
        }
    }
    gridbar(phase);                          // MMD reads all dout rows + norms + kd
    // MMD: atomic work queue over 384 units (deterministic: per-unit g_PART slot)
    for (;;){
        __syncthreads();
        if (tid == 0) s_u = atomicAdd(&g_work, 1);
        __syncthreads();
        int u = s_u;
        if (u >= 384) break;
        mmd_unit(SM.m, u, dout, rgb);
    }
    gridbar(phase);                          // final reduce reads all g_PART
    if (cta == 0 && tid < 32){
        float s[3];
        #pragma unroll
        for (int t = 0; t < 3; t++){
            float v = 0.f;
            for (int i = tid; i < 128; i += 32) v += g_PART[t*128 + i];
            #pragma unroll
            for (int off = 16; off > 0; off >>= 1) v += __shfl_xor_sync(0xffffffffu, v, off);
            s[t] = v;
        }
        if (tid == 0 && out_size > M_TOK*DM){
            const float inv = 1.f / 16777216.f;   // 1/(4096*4096)
            float s0 = 2.f*s[0] + 4096.f;         // strict-upper -> full (sym + diag)
            float s1 = 2.f*s[1] + 4096.f;
            dout[M_TOK*DM] = (s0 + s1 - 2.f*s[2]) * inv;
        }
    }
}

// ---------------- host orchestration ---------------------------------------------
extern "C" void kernel_launch(void* const* d_in, const int* in_sizes, int n_in,
                              void* d_out, int out_size)
{
    (void)in_sizes; (void)n_in;
    const float* hsi  = (const float*)d_in[0];
    const float* rgb  = (const float*)d_in[1];
    const float* in_w = (const float*)d_in[2];
    const float* in_b = (const float*)d_in[3];
    const float* ow   = (const float*)d_in[4];
    const float* ob   = (const float*)d_in[5];
    const float* l1w  = (const float*)d_in[6];
    const float* l1b  = (const float*)d_in[7];
    const float* l2w  = (const float*)d_in[8];
    const float* l2b  = (const float*)d_in[9];
    const float* n1w  = (const float*)d_in[10];
    const float* n1b  = (const float*)d_in[11];
    const float* n2w  = (const float*)d_in[12];
    const float* n2b  = (const float*)d_in[13];
    const float* mask = (const float*)d_in[14];
    float* dout = (float*)d_out;

    k_init<<<1, 1>>>();
    k_mega<<<GRID, 256>>>(hsi, rgb, in_w, in_b, ow, ob, l1w, l1b, l2w, l2b,
                          n1w, n1b, n2w, n2b, mask, dout, out_size);
}

// round 17
// speedup vs baseline: 1.9314x; 1.5285x over previous
#include <cuda_runtime.h>

#define M_TOK 4096
#define DM    64
#define NH    8
#define HD    8
#define DFF   256
#define NLAYER 4
#define GRID  256

typedef unsigned long long u64;

// ---------------- scratch (device globals; no allocation allowed) ----------------
__device__ unsigned g_barcnt;
__device__ int      g_work;
__device__ __align__(16) float g_X   [M_TOK*DM];
__device__ __align__(16) float g_QKV [3*NH*M_TOK*HD];
__device__ __align__(16) float g_F1  [M_TOK*DFF];
__device__ __align__(16) float g_ATT [M_TOK*DM];
__device__ float g_NX[M_TOK];
__device__ float g_NY[M_TOK];
__device__ float g_PART[3*128];
__device__ int   g_kd;

// ---------------- packed f32x2 helpers (SASS FFMA2: only reachable via PTX) ------
#define F2_FMA(d,a,b)    asm("fma.rn.f32x2 %0,%1,%2,%0;" : "+l"(d) : "l"(a),"l"(b))
#define F2_ADD(d,a,b)    asm("add.rn.f32x2 %0,%1,%2;"    : "+l"(d) : "l"(a),"l"(b))
#define PACK2(d,lo,hi)   asm("mov.b64 %0,{%1,%2};" : "=l"(d) : "r"(lo),"r"(hi))
#define UNPACK2(lo,hi,s) asm("mov.b64 {%0,%1},%2;" : "=r"(lo),"=r"(hi) : "l"(s))
// exp2 on the MUFU pipe (concurrent with fma pipe)
#define EX2F(d,s)        asm("ex2.approx.f32 %0, %1;" : "=f"(d) : "f"(s))

// tf32 mma: D = A(16x8) * B(8x8) + C, f32 accumulate. In-place C=D form.
#define MMA_TF32(d0,d1,d2,d3,a0,a1,a2,a3,b0,b1) \
    asm("mma.sync.aligned.m16n8k8.row.col.f32.tf32.tf32.f32 " \
        "{%0,%1,%2,%3},{%4,%5,%6,%7},{%8,%9},{%0,%1,%2,%3};" \
        : "+f"(d0),"+f"(d1),"+f"(d2),"+f"(d3) \
        : "r"(a0),"r"(a1),"r"(a2),"r"(a3),"r"(b0),"r"(b1))

__device__ __forceinline__ unsigned cvt_tf32(float x){
    unsigned r; asm("cvt.rna.tf32.f32 %0, %1;" : "=r"(r) : "f"(x)); return r;
}

#define LOG2E  1.4426950408889634f
#define NL2EH -0.7213475204444817f    // -log2(e)/2

// ---------------- shared memory union --------------------------------------------
struct GemmS { float A[16][68]; float W[64][66]; };
struct AttnS { unsigned Ks[512*8]; unsigned Vs[512*8]; };   // 32 KB (tf32 bits)
struct MmdS  { float A[32][68]; float B[128][68]; float na[32]; float nb[128]; float red[256]; };
union SmemU { GemmS g; AttnS a; MmdS m; };

// ---------------- grid barrier: release-arrive + acquire-load poll ---------------
__device__ __forceinline__ void gridbar(unsigned& phase){
    __syncthreads();
    phase += 1;
    if (threadIdx.x == 0){
        __threadfence();
        atomicAdd(&g_barcnt, 1u);
        const unsigned target = phase*GRID;
        unsigned v;
        do {
            asm volatile("ld.global.acquire.gpu.u32 %0, [%1];"
                         : "=r"(v) : "l"(&g_barcnt));
        } while (v < target);
    }
    __syncthreads();
}

// ---------------- 16-row GEMM tile: C[rb..rb+16, cb..cb+64] = A @ W^T + b --------
// EPI 0: scatter to Q/K/V head layout (q scaled by log2e/sqrt(hd)); EPI 1: ReLU;
// EPI 2: +res, LN; EPI 4: +res, LN, *mask -> OUT(dout), row norms NX/NY.
template<int KDIM, int EPI>
__device__ __forceinline__ void gemm16(
    GemmS& S, int rb, int cb, int slice,
    const float* __restrict__ A,
    const float* __restrict__ W,
    const float* __restrict__ bias,
    const float* __restrict__ RES,
    const float* __restrict__ lnw, const float* __restrict__ lnb,
    float* __restrict__ OUT, int ldo,
    const float* __restrict__ mask, const float* __restrict__ RGB)
{
    const int tid = threadIdx.x;
    const int c0  = tid & 31;
    const int rbase = (tid >> 5) * 2;
    u64 acc2[2][2] = {};

    __syncthreads();   // protect smem reuse from previous stage's reads
    #pragma unroll
    for (int ch = 0; ch < KDIM/64; ch++){
        {
            int r = tid >> 4, kq = tid & 15;     // 256 float4s, one per thread
            *(float4*)&S.A[r][kq*4] =
                ((const float4*)(A + (size_t)(rb + r)*KDIM + ch*64))[kq];
        }
        #pragma unroll
        for (int idx = tid; idx < 4096; idx += 256){
            int c = idx >> 6, k = idx & 63;
            S.W[c][k] = W[(size_t)(cb + c)*KDIM + ch*64 + k];
        }
        __syncthreads();
        #pragma unroll
        for (int k = 0; k < 64; k += 4){
            ulonglong2 a0 = *(const ulonglong2*)&S.A[rbase+0][k];
            ulonglong2 a1 = *(const ulonglong2*)&S.A[rbase+1][k];
            u64 w0a = *(const u64*)&S.W[c0   ][k];
            u64 w0b = *(const u64*)&S.W[c0   ][k+2];
            u64 w1a = *(const u64*)&S.W[c0+32][k];
            u64 w1b = *(const u64*)&S.W[c0+32][k+2];
            F2_FMA(acc2[0][0], a0.x, w0a); F2_FMA(acc2[0][0], a0.y, w0b);
            F2_FMA(acc2[0][1], a0.x, w1a); F2_FMA(acc2[0][1], a0.y, w1b);
            F2_FMA(acc2[1][0], a1.x, w0a); F2_FMA(acc2[1][0], a1.y, w0b);
            F2_FMA(acc2[1][1], a1.x, w1a); F2_FMA(acc2[1][1], a1.y, w1b);
        }
        __syncthreads();
    }

    // Q scale folds 1/sqrt(hd) AND log2(e): logits come out in exp2 domain.
    const float qs = (EPI == 0 && slice == 0) ? 0.51012678299116750f : 1.0f;
    #pragma unroll
    for (int i = 0; i < 2; i++){
        int m = rb + rbase + i;
        #pragma unroll
        for (int u = 0; u < 2; u++){
            int c = c0 + 32*u;
            unsigned lo, hi;
            UNPACK2(lo, hi, acc2[i][u]);
            float v = __uint_as_float(lo) + __uint_as_float(hi) + bias[cb + c];
            if (EPI == 0){
                v *= qs;
                OUT[((slice*NH + (c >> 3))*M_TOK + m)*HD + (c & 7)] = v;
            } else if (EPI == 1){
                OUT[(size_t)m*ldo + cb + c] = fmaxf(v, 0.f);
            } else {
                S.A[rbase+i][c] = v + RES[m*DM + c];
            }
        }
    }
    if (EPI >= 2){
        __syncthreads();
        int row = tid >> 4, seg = tid & 15;
        float s = 0.f, s2 = 0.f;
        #pragma unroll
        for (int t = 0; t < 4; t++){
            float x = S.A[row][seg*4 + t];
            s += x; s2 = fmaf(x, x, s2);
        }
        #pragma unroll
        for (int off = 8; off > 0; off >>= 1){
            s  += __shfl_xor_sync(0xffffffffu, s,  off);
            s2 += __shfl_xor_sync(0xffffffffu, s2, off);
        }
        float mean = s * (1.f/64.f);
        float var  = fmaf(-mean, mean, s2 * (1.f/64.f));
        float rstd = rsqrtf(var + 1e-5f);
        int m = rb + row;
        if (EPI == 2){
            #pragma unroll
            for (int t = 0; t < 4; t++){
                int c = seg*4 + t;
                OUT[m*DM + c] = (S.A[row][c] - mean) * rstd * lnw[c] + lnb[c];
            }
        } else {   // EPI 4: prune, emit output, row norms
            float nx = 0.f, ny = 0.f;
            #pragma unroll
            for (int t = 0; t < 4; t++){
                int c = seg*4 + t;
                float o  = (S.A[row][c] - mean) * rstd * lnw[c] + lnb[c];
                float xv = o * mask[c];
                OUT[m*DM + c] = xv;
                float yv = RGB[m*DM + c];
                nx = fmaf(xv, xv, nx);
                ny = fmaf(yv, yv, ny);
            }
            #pragma unroll
            for (int off = 8; off > 0; off >>= 1){
                nx += __shfl_xor_sync(0xffffffffu, nx, off);
                ny += __shfl_xor_sync(0xffffffffu, ny, off);
            }
            if (seg == 0){ g_NX[m] = nx; g_NY[m] = ny; }
        }
    }
}

// ---------------- attention unit: tf32 tensor-core flash (no-max softmax) --------
// CTA = (head h, 128-query block). Warp = 16 queries. Full 4096 keys, tiles of 512.
// QK: mma.m16n8k8 (K=8 one step). P = exp2(S) via MUFU, truncated to tf32 by mask.
// PV: S fragment reused as A operand; V rows permuted [0,2,4,6,1,3,5,7] per 8-key
// chunk so C-layout (cols 2t,2t+1) matches A-layout (k=t,t+4). A order (c0,c2,c1,c3).
// ssum accumulated from TRUNCATED P so normalization cancels truncation bias.
__device__ __forceinline__ void attn_unit(AttnS& S, const float* __restrict__ QKV, int u)
{
    const int tid = threadIdx.x, lane = tid & 31, wid = tid >> 5;
    const int h = u & 7, qb = u >> 3;
    const int g = lane >> 2, t = lane & 3;
    const int mq = qb*128 + wid*16;
    const float*  Q  = QKV + ((size_t)h*M_TOK + mq)*HD;
    const float4* K4 = (const float4*)(QKV + ((size_t)(NH   + h)*M_TOK)*HD);
    const float4* V4 = (const float4*)(QKV + ((size_t)(2*NH + h)*M_TOK)*HD);

    unsigned qa0 = cvt_tf32(Q[(g    )*HD + t]);
    unsigned qa1 = cvt_tf32(Q[(g + 8)*HD + t]);
    unsigned qa2 = cvt_tf32(Q[(g    )*HD + t + 4]);
    unsigned qa3 = cvt_tf32(Q[(g + 8)*HD + t + 4]);

    float o0=0.f,o1=0.f,o2=0.f,o3=0.f, ss0=0.f, ss1=0.f;

    __syncthreads();
    for (int kt = 0; kt < 8; kt++){
        const int key0 = kt*512;
        for (int idx = tid; idx < 1024; idx += 256){    // 512 keys x 2 float4
            float4 kv = K4[key0*2 + idx];
            uint4 kb;
            kb.x = cvt_tf32(kv.x); kb.y = cvt_tf32(kv.y);
            kb.z = cvt_tf32(kv.z); kb.w = cvt_tf32(kv.w);
            *(uint4*)&S.Ks[idx*4] = kb;
            float4 vv = V4[key0*2 + idx];
            uint4 vb;
            vb.x = cvt_tf32(vv.x); vb.y = cvt_tf32(vv.y);
            vb.z = cvt_tf32(vv.z); vb.w = cvt_tf32(vv.w);
            *(uint4*)&S.Vs[idx*4] = vb;
        }
        __syncthreads();
        #pragma unroll 4
        for (int j = 0; j < 64; j++){
            // QK: B frag = K[key j*8+g][dim t], [dim t+4]
            unsigned kb0 = S.Ks[(j*8 + g)*8 + t];
            unsigned kb1 = S.Ks[(j*8 + g)*8 + t + 4];
            float s0=0.f, s1=0.f, s2=0.f, s3=0.f;
            MMA_TF32(s0,s1,s2,s3, qa0,qa1,qa2,qa3, kb0,kb1);
            float p0,p1,p2,p3;
            EX2F(p0,s0); EX2F(p1,s1); EX2F(p2,s2); EX2F(p3,s3);
            unsigned u0 = __float_as_uint(p0) & 0xFFFFE000u;
            unsigned u1 = __float_as_uint(p1) & 0xFFFFE000u;
            unsigned u2 = __float_as_uint(p2) & 0xFFFFE000u;
            unsigned u3 = __float_as_uint(p3) & 0xFFFFE000u;
            ss0 += __uint_as_float(u0) + __uint_as_float(u1);
            ss1 += __uint_as_float(u2) + __uint_as_float(u3);
            // PV: B frag rows permuted — k=t -> key 2t, k=t+4 -> key 2t+1
            unsigned vb0 = S.Vs[(j*8 + 2*t    )*8 + g];
            unsigned vb1 = S.Vs[(j*8 + 2*t + 1)*8 + g];
            MMA_TF32(o0,o1,o2,o3, u0,u2,u1,u3, vb0,vb1);
        }
        __syncthreads();
    }
    // row sums: reduce over the 4-thread column group (t = 0..3)
    ss0 += __shfl_xor_sync(0xffffffffu, ss0, 1);
    ss0 += __shfl_xor_sync(0xffffffffu, ss0, 2);
    ss1 += __shfl_xor_sync(0xffffffffu, ss1, 1);
    ss1 += __shfl_xor_sync(0xffffffffu, ss1, 2);
    float i0 = 1.f/ss0, i1 = 1.f/ss1;
    int m0 = mq + g, m1 = mq + g + 8;
    *(float2*)&g_ATT[m0*DM + h*HD + 2*t] = make_float2(o0*i0, o1*i0);
    *(float2*)&g_ATT[m1*DM + h*HD + 2*t] = make_float2(o2*i1, o3*i1);
}

// ---------------- Gaussian-kernel gram sums (f32x2 dots; EX2 on MUFU) ------------
template<int KD, int SYM>
__device__ __forceinline__ u64 mmd_tile(const float (*Asm)[68], const float (*Bsm)[68],
                                        const float* na, const float* nb,
                                        int rbase, int ja, int ibase, int jbase)
{
    u64 acc2[4][4] = {};
    #pragma unroll
    for (int k = 0; k < KD; k += 4){
        ulonglong2 a0 = *(const ulonglong2*)&Asm[rbase+0][k];
        ulonglong2 a1 = *(const ulonglong2*)&Asm[rbase+1][k];
        ulonglong2 a2 = *(const ulonglong2*)&Asm[rbase+2][k];
        ulonglong2 a3 = *(const ulonglong2*)&Asm[rbase+3][k];
        ulonglong2 b0 = *(const ulonglong2*)&Bsm[ja    ][k];
        ulonglong2 b1 = *(const ulonglong2*)&Bsm[ja+32 ][k];
        ulonglong2 b2 = *(const ulonglong2*)&Bsm[ja+64 ][k];
        ulonglong2 b3 = *(const ulonglong2*)&Bsm[ja+96 ][k];
        F2_FMA(acc2[0][0], a0.x, b0.x); F2_FMA(acc2[0][0], a0.y, b0.y);
        F2_FMA(acc2[0][1], a0.x, b1.x); F2_FMA(acc2[0][1], a0.y, b1.y);
        F2_FMA(acc2[0][2], a0.x, b2.x); F2_FMA(acc2[0][2], a0.y, b2.y);
        F2_FMA(acc2[0][3], a0.x, b3.x); F2_FMA(acc2[0][3], a0.y, b3.y);
        F2_FMA(acc2[1][0], a1.x, b0.x); F2_FMA(acc2[1][0], a1.y, b0.y);
        F2_FMA(acc2[1][1], a1.x, b1.x); F2_FMA(acc2[1][1], a1.y, b1.y);
        F2_FMA(acc2[1][2], a1.x, b2.x); F2_FMA(acc2[1][2], a1.y, b2.y);
        F2_FMA(acc2[1][3], a1.x, b3.x); F2_FMA(acc2[1][3], a1.y, b3.y);
        F2_FMA(acc2[2][0], a2.x, b0.x); F2_FMA(acc2[2][0], a2.y, b0.y);
        F2_FMA(acc2[2][1], a2.x, b1.x); F2_FMA(acc2[2][1], a2.y, b1.y);
        F2_FMA(acc2[2][2], a2.x, b2.x); F2_FMA(acc2[2][2], a2.y, b2.y);
        F2_FMA(acc2[2][3], a2.x, b3.x); F2_FMA(acc2[2][3], a2.y, b3.y);
        F2_FMA(acc2[3][0], a3.x, b0.x); F2_FMA(acc2[3][0], a3.y, b0.y);
        F2_FMA(acc2[3][1], a3.x, b1.x); F2_FMA(acc2[3][1], a3.y, b1.y);
        F2_FMA(acc2[3][2], a3.x, b2.x); F2_FMA(acc2[3][2], a3.y, b2.y);
        F2_FMA(acc2[3][3], a3.x, b3.x); F2_FMA(acc2[3][3], a3.y, b3.y);
    }
    u64 psum2 = 0;
    #pragma unroll
    for (int i = 0; i < 4; i++){
        float nai = na[rbase+i];
        float p[4];
        #pragma unroll
        for (int u = 0; u < 4; u++){
            unsigned lo, hi; UNPACK2(lo, hi, acc2[i][u]);
            float dot = __uint_as_float(lo) + __uint_as_float(hi);
            float x = fmaf(dot, LOG2E, nai + nb[ja + 32*u]);
            if (SYM){
                if (jbase + 32*u <= ibase + i) x = -200.f;   // exp2 -> 0
            }
            EX2F(p[u], x);
        }
        u64 s01, s23;
        PACK2(s01, __float_as_uint(p[0]), __float_as_uint(p[1]));
        PACK2(s23, __float_as_uint(p[2]), __float_as_uint(p[3]));
        F2_ADD(psum2, psum2, s01);
        F2_ADD(psum2, psum2, s23);
    }
    return psum2;
}

__device__ __forceinline__ void mmd_unit(MmdS& S, int u,
                                         const float* __restrict__ XP,
                                         const float* __restrict__ RGB)
{
    const int type = u >> 7, ib4 = u & 127;
    const float *A, *B, *NA, *NB;
    if (type == 0){ A = XP;  B = XP;  NA = g_NX; NB = g_NX; }
    else if (type == 1){ A = RGB; B = RGB; NA = g_NY; NB = g_NY; }
    else { A = XP; B = RGB; NA = g_NX; NB = g_NY; }
    const int kd  = (type == 1) ? 64 : g_kd;
    const int sym = (type != 2);

    const int tid = threadIdx.x;
    const int ib  = ib4 * 32;
    for (int idx = tid; idx < 512; idx += 256){
        int r = idx >> 4, kq = idx & 15;
        *(float4*)&S.A[r][kq*4] = ((const float4*)A)[(ib + r)*16 + kq];
    }
    if (tid < 32) S.na[tid] = NA[ib + tid] * NL2EH;    // pre-scale: -log2e/2 * ||a||^2

    const int ja = tid & 31, rbase = (tid >> 5) * 4;
    const int ibase = ib + rbase;
    u64 psum2 = 0;
    for (int jt = 0; jt < 32; jt++){
        if (sym && jt*128 + 127 <= ib) continue;
        __syncthreads();
        for (int idx = tid; idx < 2048; idx += 256){
            int r = idx >> 4, kq = idx & 15;
            *(float4*)&S.B[r][kq*4] = ((const float4*)B)[(jt*128 + r)*16 + kq];
        }
        if (tid < 128) S.nb[tid] = NB[jt*128 + tid] * NL2EH;
        __syncthreads();
        const int jbase = jt*128 + ja;
        u64 t;
        if (sym){
            if (kd == 32) t = mmd_tile<32,1>(S.A, S.B, S.na, S.nb, rbase, ja, ibase, jbase);
            else          t = mmd_tile<64,1>(S.A, S.B, S.na, S.nb, rbase, ja, ibase, jbase);
        } else {
            if (kd == 32) t = mmd_tile<32,0>(S.A, S.B, S.na, S.nb, rbase, ja, ibase, jbase);
            else          t = mmd_tile<64,0>(S.A, S.B, S.na, S.nb, rbase, ja, ibase, jbase);
        }
        F2_ADD(psum2, psum2, t);
    }
    unsigned lo, hi; UNPACK2(lo, hi, psum2);
    __syncthreads();
    S.red[tid] = __uint_as_float(lo) + __uint_as_float(hi);
    __syncthreads();
    for (int s = 128; s > 0; s >>= 1){
        if (tid < s) S.red[tid] += S.red[tid + s];
        __syncthreads();
    }
    if (tid == 0) g_PART[type*128 + ib4] = S.red[0];
}

// ---------------- init + megakernel ----------------------------------------------
__global__ void k_init(){
    g_barcnt = 0;
    g_work = 0;
}

__global__ __launch_bounds__(256, 2) void k_mega(
    const float* __restrict__ hsi, const float* __restrict__ rgb,
    const float* __restrict__ in_w, const float* __restrict__ in_b,
    const float* __restrict__ ow,   const float* __restrict__ ob,
    const float* __restrict__ l1w,  const float* __restrict__ l1b,
    const float* __restrict__ l2w,  const float* __restrict__ l2b,
    const float* __restrict__ n1w,  const float* __restrict__ n1b,
    const float* __restrict__ n2w,  const float* __restrict__ n2b,
    const float* __restrict__ mask, float* __restrict__ dout, int out_size)
{
    __shared__ SmemU SM;
    __shared__ int s_u;
    const int cta = blockIdx.x, tid = threadIdx.x;
    const int rb = cta * 16;
    unsigned phase = 0;

    for (int l = 0; l < NLAYER; l++){
        const float* Xin = (l == 0) ? hsi : g_X;
        // QKV: 3 col-slices, q pre-scaled (log2e/sqrt(hd)), head-layout scatter
        #pragma unroll
        for (int s = 0; s < 3; s++)
            gemm16<64,0>(SM.g, rb, s*64, s, Xin, in_w + l*192*64, in_b + l*192,
                         nullptr, nullptr, nullptr, g_QKV, 0, nullptr, nullptr);
        gridbar(phase);                      // attention reads all tokens' Q/K/V
        // attention: unit = (head, 128-query block), one per CTA; writes normalized ATT
        attn_unit(SM.a, g_QKV, cta);
        gridbar(phase);                      // out-proj reads cross-CTA ATT rows
        // out-proj + residual + LN1
        gemm16<64,2>(SM.g, rb, 0, 0, g_ATT, ow + l*64*64, ob + l*64,
                     Xin, n1w + l*64, n1b + l*64, g_X, 64, nullptr, nullptr);
        // FF1 (ReLU): 4 col-slices — row-aligned with proj, no barrier needed
        #pragma unroll
        for (int s = 0; s < 4; s++)
            gemm16<64,1>(SM.g, rb, s*64, 0, g_X, l1w + l*256*64, l1b + l*256,
                         nullptr, nullptr, nullptr, g_F1, 256, nullptr, nullptr);
        // FF2 + residual + LN2 (+ final layer: prune, output, norms) — row-aligned
        if (l < NLAYER-1){
            gemm16<256,2>(SM.g, rb, 0, 0, g_F1, l2w + l*64*256, l2b + l*64,
                          g_X, n2w + l*64, n2b + l*64, g_X, 64, nullptr, nullptr);
        } else {
            gemm16<256,4>(SM.g, rb, 0, 0, g_F1, l2w + l*64*256, l2b + l*64,
                          g_X, n2w + l*64, n2b + l*64, dout, 64, mask, rgb);
            if (cta == 0 && tid < 32){
                unsigned any = __ballot_sync(0xffffffffu, mask[32 + tid] != 0.f);
                if (tid == 0) g_kd = any ? 64 : 32;
            }
        }
    }
    gridbar(phase);                          // MMD reads all dout rows + norms + kd
    // MMD: atomic work queue over 384 units (deterministic: per-unit g_PART slot)
    for (;;){
        __syncthreads();
        if (tid == 0) s_u = atomicAdd(&g_work, 1);
        __syncthreads();
        int u = s_u;
        if (u >= 384) break;
        mmd_unit(SM.m, u, dout, rgb);
    }
    gridbar(phase);                          // final reduce reads all g_PART
    if (cta == 0 && tid < 32){
        float s[3];
        #pragma unroll
        for (int t = 0; t < 3; t++){
            float v = 0.f;
            for (int i = tid; i < 128; i += 32) v += g_PART[t*128 + i];
            #pragma unroll
            for (int off = 16; off > 0; off >>= 1) v += __shfl_xor_sync(0xffffffffu, v, off);
            s[t] = v;
        }
        if (tid == 0 && out_size > M_TOK*DM){
            const float inv = 1.f / 16777216.f;   // 1/(4096*4096)
            float s0 = 2.f*s[0] + 4096.f;         // strict-upper -> full (sym + diag)
            float s1 = 2.f*s[1] + 4096.f;
            dout[M_TOK*DM] = (s0 + s1 - 2.f*s[2]) * inv;
        }
    }
}

// ---------------- host orchestration ---------------------------------------------
extern "C" void kernel_launch(void* const* d_in, const int* in_sizes, int n_in,
                              void* d_out, int out_size)
{
    (void)in_sizes; (void)n_in;
    const float* hsi  = (const float*)d_in[0];
    const float* rgb  = (const float*)d_in[1];
    const float* in_w = (const float*)d_in[2];
    const float* in_b = (const float*)d_in[3];
    const float* ow   = (const float*)d_in[4];
    const float* ob   = (const float*)d_in[5];
    const float* l1w  = (const float*)d_in[6];
    const float* l1b  = (const float*)d_in[7];
    const float* l2w  = (const float*)d_in[8];
    const float* l2b  = (const float*)d_in[9];
    const float* n1w  = (const float*)d_in[10];
    const float* n1b  = (const float*)d_in[11];
    const float* n2w  = (const float*)d_in[12];
    const float* n2b  = (const float*)d_in[13];
    const float* mask = (const float*)d_in[14];
    float* dout = (float*)d_out;

    k_init<<<1, 1>>>();
    k_mega<<<GRID, 256>>>(hsi, rgb, in_w, in_b, ow, ob, l1w, l1b, l2w, l2b,
                          n1w, n1b, n2w, n2b, mask, dout, out_size);
}